// round 1
// baseline (speedup 1.0000x reference)
#include <cuda_runtime.h>
#include <cuda_bf16.h>
#include <cstdint>

// Problem constants
#define BB 2
#define TT 2048
#define CC 1024
#define HH 16
#define DD 64

// Scratch (allocation-free rule: __device__ globals)
__device__ float g_qkv[(size_t)BB * TT * 3 * CC];   // (B,T,3C)
__device__ float g_attn[(size_t)BB * TT * CC];      // (B,T,C)
__device__ int   g_valid[BB * TT];

// ---------------------------------------------------------------------------
// Mask normalization: detect storage dtype (uint8 vs 4-byte) on device.
// lengths >= T/2 guarantees mask[1]==True, so byte index 1 nonzero <=> 1-byte
// storage. 4-byte path (nonzero word == valid) covers both int32 and float32.
// ---------------------------------------------------------------------------
__global__ void mask_convert_kernel(const unsigned char* __restrict__ raw, int n) {
    int i = blockIdx.x * blockDim.x + threadIdx.x;
    if (i >= n) return;
    bool one_byte = (raw[1] != 0);
    int v;
    if (one_byte) {
        v = (raw[i] != 0);
    } else {
        v = (((const unsigned int*)raw)[i] != 0u);
    }
    g_valid[i] = v;
}

// ---------------------------------------------------------------------------
// SGEMM (NT): C[M][N] = A[M][K] * W[N][K]^T + bias[N]
// 128x128 block tile, 256 threads, 8x8 per-thread micro-tile, K-chunk 8.
// ---------------------------------------------------------------------------
__global__ __launch_bounds__(256, 2) void sgemm_nt_bias_kernel(
    const float* __restrict__ A, const float* __restrict__ W,
    const float* __restrict__ bias, float* __restrict__ Cmat,
    int M, int N, int K)
{
    __shared__ float As[8][128];
    __shared__ float Bs[8][128];

    const int tid  = threadIdx.x;
    const int tx   = tid & 15;          // 0..15 -> N micro-tiles
    const int ty   = tid >> 4;          // 0..15 -> M micro-tiles
    const int m0   = blockIdx.y * 128;
    const int n0   = blockIdx.x * 128;
    const int lrow = tid >> 1;          // 0..127
    const int lseg = (tid & 1) * 4;     // 0 or 4

    const float* Ap = A + (size_t)(m0 + lrow) * K + lseg;
    const float* Wp = W + (size_t)(n0 + lrow) * K + lseg;

    float acc[8][8];
#pragma unroll
    for (int i = 0; i < 8; ++i)
#pragma unroll
        for (int j = 0; j < 8; ++j) acc[i][j] = 0.f;

    for (int kk = 0; kk < K; kk += 8) {
        float4 av = *(const float4*)(Ap + kk);
        float4 wv = *(const float4*)(Wp + kk);
        __syncthreads();
        As[lseg + 0][lrow] = av.x; As[lseg + 1][lrow] = av.y;
        As[lseg + 2][lrow] = av.z; As[lseg + 3][lrow] = av.w;
        Bs[lseg + 0][lrow] = wv.x; Bs[lseg + 1][lrow] = wv.y;
        Bs[lseg + 2][lrow] = wv.z; Bs[lseg + 3][lrow] = wv.w;
        __syncthreads();
#pragma unroll
        for (int k = 0; k < 8; ++k) {
            float a[8], b[8];
            *(float4*)&a[0] = *(const float4*)&As[k][ty * 8];
            *(float4*)&a[4] = *(const float4*)&As[k][ty * 8 + 4];
            *(float4*)&b[0] = *(const float4*)&Bs[k][tx * 8];
            *(float4*)&b[4] = *(const float4*)&Bs[k][tx * 8 + 4];
#pragma unroll
            for (int i = 0; i < 8; ++i)
#pragma unroll
                for (int j = 0; j < 8; ++j)
                    acc[i][j] += a[i] * b[j];
        }
    }

#pragma unroll
    for (int i = 0; i < 8; ++i) {
        size_t row = (size_t)(m0 + ty * 8 + i);
#pragma unroll
        for (int j4 = 0; j4 < 8; j4 += 4) {
            int col = n0 + tx * 8 + j4;
            float4 r;
            r.x = acc[i][j4 + 0] + bias[col + 0];
            r.y = acc[i][j4 + 1] + bias[col + 1];
            r.z = acc[i][j4 + 2] + bias[col + 2];
            r.w = acc[i][j4 + 3] + bias[col + 3];
            *(float4*)(Cmat + row * N + col) = r;
        }
    }
}

// ---------------------------------------------------------------------------
// Flash attention (fp32, online softmax), 64-query x 64-key tiles, D=64.
// 256 threads: tr=tid/16 owns 4 query rows, tc=tid%16 owns 4 cols (S) / 4
// head dims (O). Q,K stored d-major (transposed) in smem for conflict-free
// float4 reads; V row-major; P with stride 65.
// Shared: Qt(16KB) + Kt(16KB) + Vs(16KB) + Ps(16.25KB) = 65792 B dynamic.
// ---------------------------------------------------------------------------
#define ATTN_SMEM_BYTES ((3 * 64 * 64 + 64 * 65) * 4)

__global__ __launch_bounds__(256) void attn_kernel(float* __restrict__ out) {
    extern __shared__ float sh[];
    float* Qt = sh;                 // [d][r]  64*64
    float* Kt = sh + 4096;          // [d][c]  64*64
    float* Vs = sh + 8192;          // [c][d]  64*64
    float* Ps = sh + 12288;         // [r][c]  64*65
    __shared__ int vflag[64];

    const int qb = blockIdx.x;      // query tile 0..31
    const int h  = blockIdx.y;
    const int b  = blockIdx.z;
    const int tid = threadIdx.x;
    const int tr = tid >> 4, tc = tid & 15;
    const int r0 = tr * 4, c0 = tc * 4, d0 = tc * 4;

    const float* qkv = g_qkv;
    const size_t rowstride = 3 * CC;
    const float* qbase = qkv + (size_t)b * TT * rowstride + h * DD;
    const float* kbase = qbase + CC;
    const float* vbase = qbase + 2 * CC;

    // Load Q tile transposed: Qt[d][r]
    {
        int row  = tid >> 2;
        int colb = (tid & 3) * 16;
        const float* gp = qbase + (size_t)(qb * 64 + row) * rowstride + colb;
#pragma unroll
        for (int u = 0; u < 4; ++u) {
            float4 v = *(const float4*)(gp + u * 4);
            int col = colb + u * 4;
            Qt[(col + 0) * 64 + row] = v.x;
            Qt[(col + 1) * 64 + row] = v.y;
            Qt[(col + 2) * 64 + row] = v.z;
            Qt[(col + 3) * 64 + row] = v.w;
        }
    }

    float o[4][4];
    float mrun[4], lrun[4];
#pragma unroll
    for (int i = 0; i < 4; ++i) {
        mrun[i] = -1e30f; lrun[i] = 0.f;
#pragma unroll
        for (int j = 0; j < 4; ++j) o[i][j] = 0.f;
    }

    const int qg0 = qb * 64 + r0;
    const float scale = 0.125f;   // 1/sqrt(64)

    for (int kb = 0; kb <= qb; ++kb) {
        int myflag = g_valid[b * TT + kb * 64 + (tid & 63)];
        int any = __syncthreads_or(myflag);
        if (tid < 64) vflag[tid] = myflag;
        if (!any) continue;   // fully padded tile: nothing reads vflag/K/V

        // Load K (transposed) and V tiles
        {
            int row  = tid >> 2;
            int colb = (tid & 3) * 16;
            const float* kp = kbase + (size_t)(kb * 64 + row) * rowstride + colb;
            const float* vp = vbase + (size_t)(kb * 64 + row) * rowstride + colb;
#pragma unroll
            for (int u = 0; u < 4; ++u) {
                int col = colb + u * 4;
                float4 kv4 = *(const float4*)(kp + u * 4);
                Kt[(col + 0) * 64 + row] = kv4.x;
                Kt[(col + 1) * 64 + row] = kv4.y;
                Kt[(col + 2) * 64 + row] = kv4.z;
                Kt[(col + 3) * 64 + row] = kv4.w;
                float4 vv4 = *(const float4*)(vp + u * 4);
                *(float4*)&Vs[row * 64 + col] = vv4;
            }
        }
        __syncthreads();

        // S = Q K^T  (4x4 per-thread tile)
        float acc[4][4];
#pragma unroll
        for (int i = 0; i < 4; ++i)
#pragma unroll
            for (int j = 0; j < 4; ++j) acc[i][j] = 0.f;

#pragma unroll 8
        for (int d = 0; d < 64; ++d) {
            float4 q4 = *(const float4*)&Qt[d * 64 + r0];
            float4 k4 = *(const float4*)&Kt[d * 64 + c0];
            float qa[4] = {q4.x, q4.y, q4.z, q4.w};
            float ka[4] = {k4.x, k4.y, k4.z, k4.w};
#pragma unroll
            for (int i = 0; i < 4; ++i)
#pragma unroll
                for (int j = 0; j < 4; ++j)
                    acc[i][j] += qa[i] * ka[j];
        }

        // Mask + scale
        const int kg0 = kb * 64 + c0;
#pragma unroll
        for (int i = 0; i < 4; ++i)
#pragma unroll
            for (int j = 0; j < 4; ++j) {
                bool ok = (kg0 + j <= qg0 + i) && (vflag[c0 + j] != 0);
                acc[i][j] = ok ? acc[i][j] * scale : -1e30f;
            }

        // Online softmax update (16-lane groups share a query row)
#pragma unroll
        for (int i = 0; i < 4; ++i) {
            float mx = fmaxf(fmaxf(acc[i][0], acc[i][1]), fmaxf(acc[i][2], acc[i][3]));
#pragma unroll
            for (int off = 8; off >= 1; off >>= 1)
                mx = fmaxf(mx, __shfl_xor_sync(0xffffffffu, mx, off));
            float mnew  = fmaxf(mrun[i], mx);
            float alpha = __expf(mrun[i] - mnew);
            float s = 0.f;
#pragma unroll
            for (int j = 0; j < 4; ++j) {
                acc[i][j] = __expf(acc[i][j] - mnew);
                s += acc[i][j];
            }
#pragma unroll
            for (int off = 8; off >= 1; off >>= 1)
                s += __shfl_xor_sync(0xffffffffu, s, off);
            lrun[i] = lrun[i] * alpha + s;
            mrun[i] = mnew;
#pragma unroll
            for (int j = 0; j < 4; ++j) o[i][j] *= alpha;
            Ps[(r0 + i) * 65 + c0 + 0] = acc[i][0];
            Ps[(r0 + i) * 65 + c0 + 1] = acc[i][1];
            Ps[(r0 + i) * 65 + c0 + 2] = acc[i][2];
            Ps[(r0 + i) * 65 + c0 + 3] = acc[i][3];
        }
        __syncwarp();   // P row producers/consumers share a half-warp

        // O += P V
#pragma unroll 8
        for (int c = 0; c < 64; ++c) {
            float4 vv = *(const float4*)&Vs[c * 64 + d0];
#pragma unroll
            for (int i = 0; i < 4; ++i) {
                float p = Ps[(r0 + i) * 65 + c];
                o[i][0] += p * vv.x;
                o[i][1] += p * vv.y;
                o[i][2] += p * vv.z;
                o[i][3] += p * vv.w;
            }
        }
        __syncthreads();   // before next tile overwrites Kt/Vs
    }

    // Epilogue: normalize and write (B,T,C)
    float* obase = out + ((size_t)b * TT + qb * 64) * CC + h * DD;
#pragma unroll
    for (int i = 0; i < 4; ++i) {
        float inv = 1.f / lrun[i];
        float4 r;
        r.x = o[i][0] * inv; r.y = o[i][1] * inv;
        r.z = o[i][2] * inv; r.w = o[i][3] * inv;
        *(float4*)(obase + (size_t)(r0 + i) * CC + d0) = r;
    }
}

// ---------------------------------------------------------------------------
// Launch
// ---------------------------------------------------------------------------
extern "C" void kernel_launch(void* const* d_in, const int* in_sizes, int n_in,
                              void* d_out, int out_size) {
    const float*         x     = (const float*)d_in[0];
    const unsigned char* mask  = (const unsigned char*)d_in[1];
    const float*         Wqkv  = (const float*)d_in[2];
    const float*         bqkv  = (const float*)d_in[3];
    const float*         Wproj = (const float*)d_in[4];
    const float*         bproj = (const float*)d_in[5];
    float*               out   = (float*)d_out;

    float* qkv_ptr;  cudaGetSymbolAddress((void**)&qkv_ptr,  g_qkv);
    float* attn_ptr; cudaGetSymbolAddress((void**)&attn_ptr, g_attn);

    // 1. Normalize key_padding_mask -> g_valid
    {
        int n = BB * TT;
        mask_convert_kernel<<<(n + 255) / 256, 256>>>(mask, n);
    }

    // 2. QKV projection: (4096 x 1024) * (3072 x 1024)^T -> g_qkv
    {
        dim3 grid(3 * CC / 128, BB * TT / 128);
        sgemm_nt_bias_kernel<<<grid, 256>>>(x, Wqkv, bqkv, qkv_ptr,
                                            BB * TT, 3 * CC, CC);
    }

    // 3. Attention -> g_attn
    {
        cudaFuncSetAttribute(attn_kernel,
                             cudaFuncAttributeMaxDynamicSharedMemorySize,
                             ATTN_SMEM_BYTES);
        dim3 grid(TT / 64, HH, BB);
        attn_kernel<<<grid, 256, ATTN_SMEM_BYTES>>>(attn_ptr);
    }

    // 4. Output projection: (4096 x 1024) * (1024 x 1024)^T -> d_out
    {
        dim3 grid(CC / 128, BB * TT / 128);
        sgemm_nt_bias_kernel<<<grid, 256>>>(attn_ptr, Wproj, bproj, out,
                                            BB * TT, CC, CC);
    }
}

// round 3
// speedup vs baseline: 1.5897x; 1.5897x over previous
#include <cuda_runtime.h>
#include <cuda_bf16.h>
#include <cstdint>

// Problem constants
#define BB 2
#define TT 2048
#define CC 1024
#define HH 16
#define DD 64
#define MM (BB * TT)          // 4096 rows

// ---------------------------------------------------------------------------
// Scratch (__device__ globals; allocation-free rule)
// ---------------------------------------------------------------------------
__device__ float g_qkv[(size_t)BB * TT * 3 * CC];   // (B,T,3C) fp32
__device__ float g_attn[(size_t)BB * TT * CC];      // (B,T,C)  fp32
__device__ int   g_valid[BB * TT];

__device__ __nv_bfloat16 g_xhi[(size_t)MM * CC];
__device__ __nv_bfloat16 g_xlo[(size_t)MM * CC];
__device__ __nv_bfloat16 g_wqkvhi[(size_t)3 * CC * CC];
__device__ __nv_bfloat16 g_wqkvlo[(size_t)3 * CC * CC];
__device__ __nv_bfloat16 g_wprojhi[(size_t)CC * CC];
__device__ __nv_bfloat16 g_wprojlo[(size_t)CC * CC];
__device__ __nv_bfloat16 g_ahi[(size_t)MM * CC];
__device__ __nv_bfloat16 g_alo[(size_t)MM * CC];

// ---------------------------------------------------------------------------
// PTX helpers (baseline features only: valid for compute_103)
// ---------------------------------------------------------------------------
__device__ __forceinline__ uint32_t smem_u32(const void* p) {
    uint32_t a;
    asm("{ .reg .u64 t; cvta.to.shared.u64 t, %1; cvt.u32.u64 %0, t; }"
        : "=r"(a) : "l"(p));
    return a;
}

__device__ __forceinline__ void cp16(uint32_t dst, const void* src) {
    asm volatile("cp.async.cg.shared.global [%0], [%1], 16;"
                 :: "r"(dst), "l"(src) : "memory");
}
__device__ __forceinline__ void cp_commit() {
    asm volatile("cp.async.commit_group;" ::: "memory");
}
template <int N>
__device__ __forceinline__ void cp_wait() {
    asm volatile("cp.async.wait_group %0;" :: "n"(N) : "memory");
}

__device__ __forceinline__ void ldsm4(uint32_t r[4], uint32_t addr) {
    asm volatile("ldmatrix.sync.aligned.m8n8.x4.shared.b16 {%0,%1,%2,%3}, [%4];"
                 : "=r"(r[0]), "=r"(r[1]), "=r"(r[2]), "=r"(r[3]) : "r"(addr));
}

__device__ __forceinline__ void mma_bf16(float c[4],
                                         const uint32_t a[4],
                                         uint32_t b0, uint32_t b1) {
    asm volatile(
        "mma.sync.aligned.m16n8k16.row.col.f32.bf16.bf16.f32 "
        "{%0,%1,%2,%3}, {%4,%5,%6,%7}, {%8,%9}, {%0,%1,%2,%3};"
        : "+f"(c[0]), "+f"(c[1]), "+f"(c[2]), "+f"(c[3])
        : "r"(a[0]), "r"(a[1]), "r"(a[2]), "r"(a[3]), "r"(b0), "r"(b1));
}

// ---------------------------------------------------------------------------
// Mask normalization (uint8 vs 4-byte storage detection, see Round 1)
// ---------------------------------------------------------------------------
__global__ void mask_convert_kernel(const unsigned char* __restrict__ raw, int n) {
    int i = blockIdx.x * blockDim.x + threadIdx.x;
    if (i >= n) return;
    bool one_byte = (raw[1] != 0);
    int v = one_byte ? (raw[i] != 0) : (((const unsigned int*)raw)[i] != 0u);
    g_valid[i] = v;
}

// ---------------------------------------------------------------------------
// fp32 -> (bf16 hi, bf16 lo) split
// ---------------------------------------------------------------------------
__global__ void split_kernel(const float* __restrict__ in,
                             __nv_bfloat16* __restrict__ hi,
                             __nv_bfloat16* __restrict__ lo, int n4) {
    int i = blockIdx.x * blockDim.x + threadIdx.x;
    if (i >= n4) return;
    float4 v = ((const float4*)in)[i];
    __nv_bfloat16 h0 = __float2bfloat16(v.x);
    __nv_bfloat16 h1 = __float2bfloat16(v.y);
    __nv_bfloat16 h2 = __float2bfloat16(v.z);
    __nv_bfloat16 h3 = __float2bfloat16(v.w);
    __nv_bfloat16 l0 = __float2bfloat16(v.x - __bfloat162float(h0));
    __nv_bfloat16 l1 = __float2bfloat16(v.y - __bfloat162float(h1));
    __nv_bfloat16 l2 = __float2bfloat16(v.z - __bfloat162float(h2));
    __nv_bfloat16 l3 = __float2bfloat16(v.w - __bfloat162float(h3));
    ushort4 hv, lv;
    hv.x = *(unsigned short*)&h0; hv.y = *(unsigned short*)&h1;
    hv.z = *(unsigned short*)&h2; hv.w = *(unsigned short*)&h3;
    lv.x = *(unsigned short*)&l0; lv.y = *(unsigned short*)&l1;
    lv.z = *(unsigned short*)&l2; lv.w = *(unsigned short*)&l3;
    ((ushort4*)hi)[i] = hv;
    ((ushort4*)lo)[i] = lv;
}

// ---------------------------------------------------------------------------
// HMMA GEMM (NT): out[M][N] = A[M][K] * W[N][K]^T + bias, fp32 out.
// A, W as bf16 hi/lo planes; 3-pass (hh + hl + lh) into fp32 register acc.
// CTA tile 128x128, 8 warps (2M x 4N), warp tile 64x32, mma m16n8k16.
// K chunk = 64 bf16 (128B rows, SW128 swizzle), cp.async double buffer.
// ---------------------------------------------------------------------------
#define STAGE_BYTES 65536          // 4 planes x (128 rows x 128B)
#define GEMM_SMEM_DYN (2 * STAGE_BYTES + 1024)

// Stage one 128x64-bf16 plane chunk (128B/row) with SW128 swizzle via cp.async.
__device__ __forceinline__ void stage_cp(const __nv_bfloat16* __restrict__ g,
                                         uint32_t sm_dst, int row0,
                                         int k_byte0, int tid) {
#pragma unroll
    for (int u = 0; u < 4; ++u) {
        int s = u * 256 + tid;          // 0..1023 -> (row, 16B segment)
        int row = s >> 3, seg = s & 7;
        const char* src = (const char*)g +
            (size_t)(row0 + row) * (CC * 2) + k_byte0 + seg * 16;
        uint32_t off = (uint32_t)(row * 128 + seg * 16);
        uint32_t sw = off ^ ((off >> 3) & 0x70);
        cp16(sm_dst + sw, src);
    }
}

__global__ __launch_bounds__(256, 1) void gemm_mma_kernel(
    const __nv_bfloat16* __restrict__ Ahi, const __nv_bfloat16* __restrict__ Alo,
    const __nv_bfloat16* __restrict__ Whi, const __nv_bfloat16* __restrict__ Wlo,
    const float* __restrict__ bias, float* __restrict__ out, int N)
{
    extern __shared__ char dynsmem[];
    const int tid  = threadIdx.x;
    const int wid  = tid >> 5;
    const int lane = tid & 31;
    const int m0 = blockIdx.y * 128;
    const int n0 = blockIdx.x * 128;
    const int wm = (wid >> 2) * 64;     // warp row offset in CTA tile
    const int wn = (wid & 3) * 32;      // warp col offset

    uint32_t base = smem_u32(dynsmem);
    base = (base + 1023u) & ~1023u;

    float acc[4][4][4];
#pragma unroll
    for (int mt = 0; mt < 4; ++mt)
#pragma unroll
        for (int nt = 0; nt < 4; ++nt)
#pragma unroll
            for (int r = 0; r < 4; ++r) acc[mt][nt][r] = 0.f;

    // Per-lane ldmatrix addressing components
    const int sub = lane >> 3;          // which 8x8 matrix of the x4 group
    const int lr  = lane & 7;
    // A: matrices ordered [r0-7,k0],[r8-15,k0],[r0-7,k8],[r8-15,k8]
    int arow[4];  uint32_t axor[4];
#pragma unroll
    for (int mt = 0; mt < 4; ++mt) {
        arow[mt] = wm + mt * 16 + (sub & 1) * 8 + lr;
        axor[mt] = (uint32_t)((arow[mt] & 7) << 4);
    }
    const uint32_t acolH = (uint32_t)((sub >> 1) * 16);   // + ks*32
    // B: matrices ordered [n0-7,k0],[n0-7,k8],[n8-15,k0],[n8-15,k8]
    int brow[2];  uint32_t bxor[2];
#pragma unroll
    for (int np = 0; np < 2; ++np) {
        brow[np] = wn + np * 16 + (sub >> 1) * 8 + lr;
        bxor[np] = (uint32_t)((brow[np] & 7) << 4);
    }
    const uint32_t bcolH = (uint32_t)((sub & 1) * 16);    // + ks*32

    const int NC = CC / 64;             // 16 K-chunks

    // Prologue: stage chunk 0
    {
        uint32_t sb = base;
        stage_cp(Ahi, sb,          m0, 0, tid);
        stage_cp(Alo, sb + 16384,  m0, 0, tid);
        stage_cp(Whi, sb + 32768,  n0, 0, tid);
        stage_cp(Wlo, sb + 49152,  n0, 0, tid);
        cp_commit();
    }

    for (int c = 0; c < NC; ++c) {
        if (c + 1 < NC) {
            uint32_t sb = base + (uint32_t)((c + 1) & 1) * STAGE_BYTES;
            int kb = (c + 1) * 128;
            stage_cp(Ahi, sb,          m0, kb, tid);
            stage_cp(Alo, sb + 16384,  m0, kb, tid);
            stage_cp(Whi, sb + 32768,  n0, kb, tid);
            stage_cp(Wlo, sb + 49152,  n0, kb, tid);
            cp_commit();
            cp_wait<1>();
        } else {
            cp_wait<0>();
        }
        __syncthreads();

        uint32_t sb  = base + (uint32_t)(c & 1) * STAGE_BYTES;
        uint32_t aH = sb, aL = sb + 16384, bH = sb + 32768, bL = sb + 49152;

#pragma unroll
        for (int ks = 0; ks < 4; ++ks) {
            uint32_t kA = (uint32_t)(ks * 32) + acolH;
            uint32_t kB = (uint32_t)(ks * 32) + bcolH;
            uint32_t ah[4][4], al[4][4], bh[2][4], bl[2][4];
#pragma unroll
            for (int mt = 0; mt < 4; ++mt) {
                uint32_t rofs = (uint32_t)(arow[mt] * 128) + (kA ^ axor[mt]);
                ldsm4(ah[mt], aH + rofs);
                ldsm4(al[mt], aL + rofs);
            }
#pragma unroll
            for (int np = 0; np < 2; ++np) {
                uint32_t rofs = (uint32_t)(brow[np] * 128) + (kB ^ bxor[np]);
                ldsm4(bh[np], bH + rofs);
                ldsm4(bl[np], bL + rofs);
            }
#pragma unroll
            for (int mt = 0; mt < 4; ++mt)
#pragma unroll
                for (int nt = 0; nt < 4; ++nt) {
                    int np = nt >> 1, o = (nt & 1) * 2;
                    mma_bf16(acc[mt][nt], ah[mt], bh[np][o], bh[np][o + 1]);
                    mma_bf16(acc[mt][nt], ah[mt], bl[np][o], bl[np][o + 1]);
                    mma_bf16(acc[mt][nt], al[mt], bh[np][o], bh[np][o + 1]);
                }
        }
        __syncthreads();   // compute done before next restage of this buffer
    }

    // Epilogue: c-frag (c0,c1)->row=l/4, cols 2*(l%4)+{0,1}; (c2,c3)->row+8
    const int erow = m0 + wm + (lane >> 2);
    const int ecol0 = n0 + wn + (lane & 3) * 2;
#pragma unroll
    for (int mt = 0; mt < 4; ++mt) {
#pragma unroll
        for (int nt = 0; nt < 4; ++nt) {
            int row = erow + mt * 16;
            int col = ecol0 + nt * 8;
            float b0 = bias[col], b1 = bias[col + 1];
            float2 v0 = { acc[mt][nt][0] + b0, acc[mt][nt][1] + b1 };
            float2 v1 = { acc[mt][nt][2] + b0, acc[mt][nt][3] + b1 };
            *(float2*)(out + (size_t)row * N + col) = v0;
            *(float2*)(out + (size_t)(row + 8) * N + col) = v1;
        }
    }
}

// ---------------------------------------------------------------------------
// Flash attention (fp32, online softmax) — unchanged from Round 1 (passing).
// ---------------------------------------------------------------------------
#define ATTN_SMEM_BYTES ((3 * 64 * 64 + 64 * 65) * 4)

__global__ __launch_bounds__(256) void attn_kernel(float* __restrict__ out) {
    extern __shared__ float sh[];
    float* Qt = sh;                 // [d][r]  64*64
    float* Kt = sh + 4096;          // [d][c]  64*64
    float* Vs = sh + 8192;          // [c][d]  64*64
    float* Ps = sh + 12288;         // [r][c]  64*65
    __shared__ int vflag[64];

    const int qb = blockIdx.x;
    const int h  = blockIdx.y;
    const int b  = blockIdx.z;
    const int tid = threadIdx.x;
    const int tr = tid >> 4, tc = tid & 15;
    const int r0 = tr * 4, c0 = tc * 4, d0 = tc * 4;

    const float* qkv = g_qkv;
    const size_t rowstride = 3 * CC;
    const float* qbase = qkv + (size_t)b * TT * rowstride + h * DD;
    const float* kbase = qbase + CC;
    const float* vbase = qbase + 2 * CC;

    {
        int row  = tid >> 2;
        int colb = (tid & 3) * 16;
        const float* gp = qbase + (size_t)(qb * 64 + row) * rowstride + colb;
#pragma unroll
        for (int u = 0; u < 4; ++u) {
            float4 v = *(const float4*)(gp + u * 4);
            int col = colb + u * 4;
            Qt[(col + 0) * 64 + row] = v.x;
            Qt[(col + 1) * 64 + row] = v.y;
            Qt[(col + 2) * 64 + row] = v.z;
            Qt[(col + 3) * 64 + row] = v.w;
        }
    }

    float o[4][4];
    float mrun[4], lrun[4];
#pragma unroll
    for (int i = 0; i < 4; ++i) {
        mrun[i] = -1e30f; lrun[i] = 0.f;
#pragma unroll
        for (int j = 0; j < 4; ++j) o[i][j] = 0.f;
    }

    const int qg0 = qb * 64 + r0;
    const float scale = 0.125f;

    for (int kb = 0; kb <= qb; ++kb) {
        int myflag = g_valid[b * TT + kb * 64 + (tid & 63)];
        int any = __syncthreads_or(myflag);
        if (tid < 64) vflag[tid] = myflag;
        if (!any) continue;

        {
            int row  = tid >> 2;
            int colb = (tid & 3) * 16;
            const float* kp = kbase + (size_t)(kb * 64 + row) * rowstride + colb;
            const float* vp = vbase + (size_t)(kb * 64 + row) * rowstride + colb;
#pragma unroll
            for (int u = 0; u < 4; ++u) {
                int col = colb + u * 4;
                float4 kv4 = *(const float4*)(kp + u * 4);
                Kt[(col + 0) * 64 + row] = kv4.x;
                Kt[(col + 1) * 64 + row] = kv4.y;
                Kt[(col + 2) * 64 + row] = kv4.z;
                Kt[(col + 3) * 64 + row] = kv4.w;
                float4 vv4 = *(const float4*)(vp + u * 4);
                *(float4*)&Vs[row * 64 + col] = vv4;
            }
        }
        __syncthreads();

        float acc[4][4];
#pragma unroll
        for (int i = 0; i < 4; ++i)
#pragma unroll
            for (int j = 0; j < 4; ++j) acc[i][j] = 0.f;

#pragma unroll 8
        for (int d = 0; d < 64; ++d) {
            float4 q4 = *(const float4*)&Qt[d * 64 + r0];
            float4 k4 = *(const float4*)&Kt[d * 64 + c0];
            float qa[4] = {q4.x, q4.y, q4.z, q4.w};
            float ka[4] = {k4.x, k4.y, k4.z, k4.w};
#pragma unroll
            for (int i = 0; i < 4; ++i)
#pragma unroll
                for (int j = 0; j < 4; ++j)
                    acc[i][j] += qa[i] * ka[j];
        }

        const int kg0 = kb * 64 + c0;
#pragma unroll
        for (int i = 0; i < 4; ++i)
#pragma unroll
            for (int j = 0; j < 4; ++j) {
                bool ok = (kg0 + j <= qg0 + i) && (vflag[c0 + j] != 0);
                acc[i][j] = ok ? acc[i][j] * scale : -1e30f;
            }

#pragma unroll
        for (int i = 0; i < 4; ++i) {
            float mx = fmaxf(fmaxf(acc[i][0], acc[i][1]), fmaxf(acc[i][2], acc[i][3]));
#pragma unroll
            for (int off = 8; off >= 1; off >>= 1)
                mx = fmaxf(mx, __shfl_xor_sync(0xffffffffu, mx, off));
            float mnew  = fmaxf(mrun[i], mx);
            float alpha = __expf(mrun[i] - mnew);
            float s = 0.f;
#pragma unroll
            for (int j = 0; j < 4; ++j) {
                acc[i][j] = __expf(acc[i][j] - mnew);
                s += acc[i][j];
            }
#pragma unroll
            for (int off = 8; off >= 1; off >>= 1)
                s += __shfl_xor_sync(0xffffffffu, s, off);
            lrun[i] = lrun[i] * alpha + s;
            mrun[i] = mnew;
#pragma unroll
            for (int j = 0; j < 4; ++j) o[i][j] *= alpha;
            Ps[(r0 + i) * 65 + c0 + 0] = acc[i][0];
            Ps[(r0 + i) * 65 + c0 + 1] = acc[i][1];
            Ps[(r0 + i) * 65 + c0 + 2] = acc[i][2];
            Ps[(r0 + i) * 65 + c0 + 3] = acc[i][3];
        }
        __syncwarp();

#pragma unroll 8
        for (int c = 0; c < 64; ++c) {
            float4 vv = *(const float4*)&Vs[c * 64 + d0];
#pragma unroll
            for (int i = 0; i < 4; ++i) {
                float p = Ps[(r0 + i) * 65 + c];
                o[i][0] += p * vv.x;
                o[i][1] += p * vv.y;
                o[i][2] += p * vv.z;
                o[i][3] += p * vv.w;
            }
        }
        __syncthreads();
    }

    float* obase = out + ((size_t)b * TT + qb * 64) * CC + h * DD;
#pragma unroll
    for (int i = 0; i < 4; ++i) {
        float inv = 1.f / lrun[i];
        float4 r;
        r.x = o[i][0] * inv; r.y = o[i][1] * inv;
        r.z = o[i][2] * inv; r.w = o[i][3] * inv;
        *(float4*)(obase + (size_t)(r0 + i) * CC + d0) = r;
    }
}

// ---------------------------------------------------------------------------
// Launch
// ---------------------------------------------------------------------------
extern "C" void kernel_launch(void* const* d_in, const int* in_sizes, int n_in,
                              void* d_out, int out_size) {
    const float*         x     = (const float*)d_in[0];
    const unsigned char* mask  = (const unsigned char*)d_in[1];
    const float*         Wqkv  = (const float*)d_in[2];
    const float*         bqkv  = (const float*)d_in[3];
    const float*         Wproj = (const float*)d_in[4];
    const float*         bproj = (const float*)d_in[5];
    float*               out   = (float*)d_out;

    float* qkv_ptr;  cudaGetSymbolAddress((void**)&qkv_ptr,  g_qkv);
    float* attn_ptr; cudaGetSymbolAddress((void**)&attn_ptr, g_attn);
    __nv_bfloat16 *xhi, *xlo, *wqh, *wql, *wph, *wpl, *ahi, *alo;
    cudaGetSymbolAddress((void**)&xhi, g_xhi);
    cudaGetSymbolAddress((void**)&xlo, g_xlo);
    cudaGetSymbolAddress((void**)&wqh, g_wqkvhi);
    cudaGetSymbolAddress((void**)&wql, g_wqkvlo);
    cudaGetSymbolAddress((void**)&wph, g_wprojhi);
    cudaGetSymbolAddress((void**)&wpl, g_wprojlo);
    cudaGetSymbolAddress((void**)&ahi, g_ahi);
    cudaGetSymbolAddress((void**)&alo, g_alo);

    // 1. mask
    {
        int n = BB * TT;
        mask_convert_kernel<<<(n + 255) / 256, 256>>>(mask, n);
    }

    // 2. splits
    {
        int n4 = MM * CC / 4;
        split_kernel<<<(n4 + 255) / 256, 256>>>(x, xhi, xlo, n4);
        n4 = 3 * CC * CC / 4;
        split_kernel<<<(n4 + 255) / 256, 256>>>(Wqkv, wqh, wql, n4);
        n4 = CC * CC / 4;
        split_kernel<<<(n4 + 255) / 256, 256>>>(Wproj, wph, wpl, n4);
    }

    cudaFuncSetAttribute(gemm_mma_kernel,
                         cudaFuncAttributeMaxDynamicSharedMemorySize,
                         GEMM_SMEM_DYN);

    // 3. QKV projection (HMMA): (4096x1024)*(3072x1024)^T
    {
        dim3 grid(3 * CC / 128, MM / 128);
        gemm_mma_kernel<<<grid, 256, GEMM_SMEM_DYN>>>(xhi, xlo, wqh, wql,
                                                      bqkv, qkv_ptr, 3 * CC);
    }

    // 4. Attention (fp32 SIMT)
    {
        cudaFuncSetAttribute(attn_kernel,
                             cudaFuncAttributeMaxDynamicSharedMemorySize,
                             ATTN_SMEM_BYTES);
        dim3 grid(TT / 64, HH, BB);
        attn_kernel<<<grid, 256, ATTN_SMEM_BYTES>>>(attn_ptr);
    }

    // 5. split attention output
    {
        int n4 = MM * CC / 4;
        split_kernel<<<(n4 + 255) / 256, 256>>>(attn_ptr, ahi, alo, n4);
    }

    // 6. Output projection (HMMA): (4096x1024)*(1024x1024)^T
    {
        dim3 grid(CC / 128, MM / 128);
        gemm_mma_kernel<<<grid, 256, GEMM_SMEM_DYN>>>(ahi, alo, wph, wpl,
                                                      bproj, out, CC);
    }
}

// round 4
// speedup vs baseline: 1.9972x; 1.2564x over previous
#include <cuda_runtime.h>
#include <cuda_bf16.h>
#include <cstdint>

// Problem constants
#define BB 2
#define TT 2048
#define CC 1024
#define HH 16
#define DD 64
#define MM (BB * TT)          // 4096 rows

// ---------------------------------------------------------------------------
// Scratch (__device__ globals; allocation-free rule)
// ---------------------------------------------------------------------------
__device__ float g_qkv[(size_t)BB * TT * 3 * CC];   // (B,T,3C) fp32
__device__ float g_attn[(size_t)BB * TT * CC];      // (B,T,C)  fp32
__device__ int   g_valid[BB * TT];

__device__ __nv_bfloat16 g_xhi[(size_t)MM * CC];
__device__ __nv_bfloat16 g_xlo[(size_t)MM * CC];
__device__ __nv_bfloat16 g_wqkvhi[(size_t)3 * CC * CC];
__device__ __nv_bfloat16 g_wqkvlo[(size_t)3 * CC * CC];
__device__ __nv_bfloat16 g_wprojhi[(size_t)CC * CC];
__device__ __nv_bfloat16 g_wprojlo[(size_t)CC * CC];
__device__ __nv_bfloat16 g_ahi[(size_t)MM * CC];
__device__ __nv_bfloat16 g_alo[(size_t)MM * CC];

// ---------------------------------------------------------------------------
// PTX helpers (baseline features only: valid for compute_103)
// ---------------------------------------------------------------------------
__device__ __forceinline__ uint32_t smem_u32(const void* p) {
    uint32_t a;
    asm("{ .reg .u64 t; cvta.to.shared.u64 t, %1; cvt.u32.u64 %0, t; }"
        : "=r"(a) : "l"(p));
    return a;
}

__device__ __forceinline__ void cp16(uint32_t dst, const void* src) {
    asm volatile("cp.async.cg.shared.global [%0], [%1], 16;"
                 :: "r"(dst), "l"(src) : "memory");
}
__device__ __forceinline__ void cp_commit() {
    asm volatile("cp.async.commit_group;" ::: "memory");
}
template <int N>
__device__ __forceinline__ void cp_wait() {
    asm volatile("cp.async.wait_group %0;" :: "n"(N) : "memory");
}

__device__ __forceinline__ void ldsm4(uint32_t r[4], uint32_t addr) {
    asm volatile("ldmatrix.sync.aligned.m8n8.x4.shared.b16 {%0,%1,%2,%3}, [%4];"
                 : "=r"(r[0]), "=r"(r[1]), "=r"(r[2]), "=r"(r[3]) : "r"(addr));
}

__device__ __forceinline__ void ldsm4t(uint32_t r[4], uint32_t addr) {
    asm volatile("ldmatrix.sync.aligned.m8n8.x4.trans.shared.b16 {%0,%1,%2,%3}, [%4];"
                 : "=r"(r[0]), "=r"(r[1]), "=r"(r[2]), "=r"(r[3]) : "r"(addr));
}

__device__ __forceinline__ void mma_bf16(float c[4],
                                         const uint32_t a[4],
                                         uint32_t b0, uint32_t b1) {
    asm volatile(
        "mma.sync.aligned.m16n8k16.row.col.f32.bf16.bf16.f32 "
        "{%0,%1,%2,%3}, {%4,%5,%6,%7}, {%8,%9}, {%0,%1,%2,%3};"
        : "+f"(c[0]), "+f"(c[1]), "+f"(c[2]), "+f"(c[3])
        : "r"(a[0]), "r"(a[1]), "r"(a[2]), "r"(a[3]), "r"(b0), "r"(b1));
}

// Pack two fp32 into bf16x2 hi plane + residual lo plane.
__device__ __forceinline__ void cvt_hilo(float e0, float e1,
                                         uint32_t& hi, uint32_t& lo) {
    asm("cvt.rn.bf16x2.f32 %0, %1, %2;" : "=r"(hi) : "f"(e1), "f"(e0));
    float h0 = __uint_as_float(hi << 16);
    float h1 = __uint_as_float(hi & 0xFFFF0000u);
    float r0 = e0 - h0, r1 = e1 - h1;
    asm("cvt.rn.bf16x2.f32 %0, %1, %2;" : "=r"(lo) : "f"(r1), "f"(r0));
}

__device__ __forceinline__ void sts64(uint32_t addr, uint32_t a, uint32_t b) {
    asm volatile("st.shared.v2.b32 [%0], {%1,%2};" :: "r"(addr), "r"(a), "r"(b)
                 : "memory");
}

// ---------------------------------------------------------------------------
// Mask normalization (uint8 vs 4-byte storage detection)
// ---------------------------------------------------------------------------
__global__ void mask_convert_kernel(const unsigned char* __restrict__ raw, int n) {
    int i = blockIdx.x * blockDim.x + threadIdx.x;
    if (i >= n) return;
    bool one_byte = (raw[1] != 0);
    int v = one_byte ? (raw[i] != 0) : (((const unsigned int*)raw)[i] != 0u);
    g_valid[i] = v;
}

// ---------------------------------------------------------------------------
// fp32 -> (bf16 hi, bf16 lo) split
// ---------------------------------------------------------------------------
__global__ void split_kernel(const float* __restrict__ in,
                             __nv_bfloat16* __restrict__ hi,
                             __nv_bfloat16* __restrict__ lo, int n4) {
    int i = blockIdx.x * blockDim.x + threadIdx.x;
    if (i >= n4) return;
    float4 v = ((const float4*)in)[i];
    uint32_t h0, l0, h1, l1;
    cvt_hilo(v.x, v.y, h0, l0);
    cvt_hilo(v.z, v.w, h1, l1);
    ((uint2*)hi)[i] = make_uint2(h0, h1);
    ((uint2*)lo)[i] = make_uint2(l0, l1);
}

// ---------------------------------------------------------------------------
// HMMA GEMM (NT): out[M][N] = A[M][K] * W[N][K]^T + bias, fp32 out.
// (unchanged from Round 3 — validated)
// ---------------------------------------------------------------------------
#define STAGE_BYTES 65536
#define GEMM_SMEM_DYN (2 * STAGE_BYTES + 1024)

__device__ __forceinline__ void stage_cp(const __nv_bfloat16* __restrict__ g,
                                         uint32_t sm_dst, int row0,
                                         int k_byte0, int tid) {
#pragma unroll
    for (int u = 0; u < 4; ++u) {
        int s = u * 256 + tid;
        int row = s >> 3, seg = s & 7;
        const char* src = (const char*)g +
            (size_t)(row0 + row) * (CC * 2) + k_byte0 + seg * 16;
        uint32_t off = (uint32_t)(row * 128 + seg * 16);
        uint32_t sw = off ^ ((off >> 3) & 0x70);
        cp16(sm_dst + sw, src);
    }
}

__global__ __launch_bounds__(256, 1) void gemm_mma_kernel(
    const __nv_bfloat16* __restrict__ Ahi, const __nv_bfloat16* __restrict__ Alo,
    const __nv_bfloat16* __restrict__ Whi, const __nv_bfloat16* __restrict__ Wlo,
    const float* __restrict__ bias, float* __restrict__ out, int N)
{
    extern __shared__ char dynsmem[];
    const int tid  = threadIdx.x;
    const int wid  = tid >> 5;
    const int lane = tid & 31;
    const int m0 = blockIdx.y * 128;
    const int n0 = blockIdx.x * 128;
    const int wm = (wid >> 2) * 64;
    const int wn = (wid & 3) * 32;

    uint32_t base = smem_u32(dynsmem);
    base = (base + 1023u) & ~1023u;

    float acc[4][4][4];
#pragma unroll
    for (int mt = 0; mt < 4; ++mt)
#pragma unroll
        for (int nt = 0; nt < 4; ++nt)
#pragma unroll
            for (int r = 0; r < 4; ++r) acc[mt][nt][r] = 0.f;

    const int sub = lane >> 3;
    const int lr  = lane & 7;
    int arow[4];  uint32_t axor[4];
#pragma unroll
    for (int mt = 0; mt < 4; ++mt) {
        arow[mt] = wm + mt * 16 + (sub & 1) * 8 + lr;
        axor[mt] = (uint32_t)((arow[mt] & 7) << 4);
    }
    const uint32_t acolH = (uint32_t)((sub >> 1) * 16);
    int brow[2];  uint32_t bxor[2];
#pragma unroll
    for (int np = 0; np < 2; ++np) {
        brow[np] = wn + np * 16 + (sub >> 1) * 8 + lr;
        bxor[np] = (uint32_t)((brow[np] & 7) << 4);
    }
    const uint32_t bcolH = (uint32_t)((sub & 1) * 16);

    const int NC = CC / 64;

    {
        uint32_t sb = base;
        stage_cp(Ahi, sb,          m0, 0, tid);
        stage_cp(Alo, sb + 16384,  m0, 0, tid);
        stage_cp(Whi, sb + 32768,  n0, 0, tid);
        stage_cp(Wlo, sb + 49152,  n0, 0, tid);
        cp_commit();
    }

    for (int c = 0; c < NC; ++c) {
        if (c + 1 < NC) {
            uint32_t sb = base + (uint32_t)((c + 1) & 1) * STAGE_BYTES;
            int kb = (c + 1) * 128;
            stage_cp(Ahi, sb,          m0, kb, tid);
            stage_cp(Alo, sb + 16384,  m0, kb, tid);
            stage_cp(Whi, sb + 32768,  n0, kb, tid);
            stage_cp(Wlo, sb + 49152,  n0, kb, tid);
            cp_commit();
            cp_wait<1>();
        } else {
            cp_wait<0>();
        }
        __syncthreads();

        uint32_t sb  = base + (uint32_t)(c & 1) * STAGE_BYTES;
        uint32_t aH = sb, aL = sb + 16384, bH = sb + 32768, bL = sb + 49152;

#pragma unroll
        for (int ks = 0; ks < 4; ++ks) {
            uint32_t kA = (uint32_t)(ks * 32) + acolH;
            uint32_t kB = (uint32_t)(ks * 32) + bcolH;
            uint32_t ah[4][4], al[4][4], bh[2][4], bl[2][4];
#pragma unroll
            for (int mt = 0; mt < 4; ++mt) {
                uint32_t rofs = (uint32_t)(arow[mt] * 128) + (kA ^ axor[mt]);
                ldsm4(ah[mt], aH + rofs);
                ldsm4(al[mt], aL + rofs);
            }
#pragma unroll
            for (int np = 0; np < 2; ++np) {
                uint32_t rofs = (uint32_t)(brow[np] * 128) + (kB ^ bxor[np]);
                ldsm4(bh[np], bH + rofs);
                ldsm4(bl[np], bL + rofs);
            }
#pragma unroll
            for (int mt = 0; mt < 4; ++mt)
#pragma unroll
                for (int nt = 0; nt < 4; ++nt) {
                    int np = nt >> 1, o = (nt & 1) * 2;
                    mma_bf16(acc[mt][nt], ah[mt], bh[np][o], bh[np][o + 1]);
                    mma_bf16(acc[mt][nt], ah[mt], bl[np][o], bl[np][o + 1]);
                    mma_bf16(acc[mt][nt], al[mt], bh[np][o], bh[np][o + 1]);
                }
        }
        __syncthreads();
    }

    const int erow = m0 + wm + (lane >> 2);
    const int ecol0 = n0 + wn + (lane & 3) * 2;
#pragma unroll
    for (int mt = 0; mt < 4; ++mt) {
#pragma unroll
        for (int nt = 0; nt < 4; ++nt) {
            int row = erow + mt * 16;
            int col = ecol0 + nt * 8;
            float b0 = bias[col], b1 = bias[col + 1];
            float2 v0 = { acc[mt][nt][0] + b0, acc[mt][nt][1] + b1 };
            float2 v1 = { acc[mt][nt][2] + b0, acc[mt][nt][3] + b1 };
            *(float2*)(out + (size_t)row * N + col) = v0;
            *(float2*)(out + (size_t)(row + 8) * N + col) = v1;
        }
    }
}

// ---------------------------------------------------------------------------
// HMMA flash attention. CTA: 128 queries x one (b,h). 8 warps, warp = 16 q
// rows x full 64-key tile (softmax warp-local). bf16 hi/lo 3-pass for both
// QK^T and PV; S frags reused as P A-frags; V via ldmatrix.trans.
// smem: Qhi/Qlo 16KB each, Khi/Klo 8KB each, Vhi/Vlo 8KB each = 64KB.
// ---------------------------------------------------------------------------
#define A_QHI 0
#define A_QLO 16384
#define A_KHI 32768
#define A_KLO 40960
#define A_VHI 49152
#define A_VLO 57344
#define ATTN2_SMEM (65536 + 1024)

__global__ __launch_bounds__(256) void attn_mma_kernel(float* __restrict__ out) {
    extern __shared__ char asmem[];
    __shared__ int vflag[64];

    uint32_t sb = smem_u32(asmem);
    sb = (sb + 1023u) & ~1023u;

    const int tid  = threadIdx.x;
    const int wid  = tid >> 5;
    const int lane = tid & 31;
    const int qb = 15 - blockIdx.x;       // heavy tiles first
    const int h  = blockIdx.y;
    const int b  = blockIdx.z;
    const int wq = wid * 16;

    const float* base = g_qkv + (size_t)b * TT * (3 * CC) + h * DD;

    // ---- Stage Q tile (128 x 64) as bf16 hi/lo, SW128 rows ----
#pragma unroll
    for (int u = 0; u < 8; ++u) {
        int s = u * 256 + tid;
        int row = s >> 4, cg = (s & 15) * 4;
        const float* gp = base + (size_t)(qb * 128 + row) * (3 * CC) + cg;
        float4 v = *(const float4*)gp;
        uint32_t h0, l0, h1, l1;
        cvt_hilo(v.x, v.y, h0, l0);
        cvt_hilo(v.z, v.w, h1, l1);
        uint32_t off = (uint32_t)(row * 128 + ((cg * 2) ^ ((row & 7) << 4)));
        sts64(sb + A_QHI + off, h0, h1);
        sts64(sb + A_QLO + off, l0, l1);
    }

    // Fragment bookkeeping
    const int sub = lane >> 3;
    const int lr  = lane & 7;
    // A (Q / P): row within warp tile
    const uint32_t a_row = (uint32_t)(wq + ((sub & 1) << 3) + lr);
    const uint32_t a_colH = (uint32_t)((sub >> 1) << 4);    // bytes
    const uint32_t a_xor = (uint32_t)((lr) << 4);
    // B (K): key row
    const uint32_t b_rowH = (uint32_t)(((sub >> 1) << 3) + lr);  // + np*16
    const uint32_t b_colH = (uint32_t)((sub & 1) << 4);          // + kt*32
    // B (V, trans): key row and d-col
    const int vt = lane >> 3, vlr = lane & 7;
    const uint32_t v_rowH = (uint32_t)(((vt & 1) << 3) + vlr);   // + kt*16
    const uint32_t v_colH = (uint32_t)((vt >> 1) << 4);          // + j2*32
    const uint32_t v_xor = (uint32_t)(vlr << 4);

    const int r   = lane >> 2;
    const int c0l = (lane & 3) * 2;
    const int qg0 = qb * 128 + wq + r;
    const int qg1 = qg0 + 8;
    const float scale = 0.125f;

    float oacc[8][4];
#pragma unroll
    for (int j = 0; j < 8; ++j)
#pragma unroll
        for (int e = 0; e < 4; ++e) oacc[j][e] = 0.f;
    float m0 = -1e30f, m1 = -1e30f, l0 = 0.f, l1 = 0.f;

    const int niter = 2 * qb + 2;
    for (int kb = 0; kb < niter; ++kb) {
        int my = (tid < 64) ? g_valid[b * TT + kb * 64 + tid] : 0;
        int any = __syncthreads_or(my);   // also fences previous compute
        if (tid < 64) vflag[tid] = my;
        if (!any) continue;

        // ---- Stage K and V tiles (64 x 64 each) ----
#pragma unroll
        for (int u = 0; u < 4; ++u) {
            int s = u * 256 + tid;
            int row = s >> 4, cg = (s & 15) * 4;
            const float* kp = base + CC +
                (size_t)(kb * 64 + row) * (3 * CC) + cg;
            const float* vp = kp + CC;
            uint32_t off = (uint32_t)(row * 128 + ((cg * 2) ^ ((row & 7) << 4)));
            float4 kv = *(const float4*)kp;
            uint32_t h0, lo0, h1, lo1;
            cvt_hilo(kv.x, kv.y, h0, lo0);
            cvt_hilo(kv.z, kv.w, h1, lo1);
            sts64(sb + A_KHI + off, h0, h1);
            sts64(sb + A_KLO + off, lo0, lo1);
            float4 vv = *(const float4*)vp;
            cvt_hilo(vv.x, vv.y, h0, lo0);
            cvt_hilo(vv.z, vv.w, h1, lo1);
            sts64(sb + A_VHI + off, h0, h1);
            sts64(sb + A_VLO + off, lo0, lo1);
        }
        __syncthreads();

        // ---- S = Q K^T (3-pass hi/lo) ----
        float sacc[8][4];
#pragma unroll
        for (int j = 0; j < 8; ++j)
#pragma unroll
            for (int e = 0; e < 4; ++e) sacc[j][e] = 0.f;

#pragma unroll
        for (int kt = 0; kt < 4; ++kt) {
            uint32_t aofs = a_row * 128 + (((uint32_t)(kt * 32) + a_colH) ^ a_xor);
            uint32_t ah[4], al[4];
            ldsm4(ah, sb + A_QHI + aofs);
            ldsm4(al, sb + A_QLO + aofs);
#pragma unroll
            for (int np = 0; np < 4; ++np) {
                uint32_t brow = (uint32_t)(np * 16) + b_rowH;
                uint32_t bofs = brow * 128 +
                    (((uint32_t)(kt * 32) + b_colH) ^ ((brow & 7) << 4));
                uint32_t bh[4], bl[4];
                ldsm4(bh, sb + A_KHI + bofs);
                ldsm4(bl, sb + A_KLO + bofs);
                mma_bf16(sacc[2 * np],     ah, bh[0], bh[1]);
                mma_bf16(sacc[2 * np],     ah, bl[0], bl[1]);
                mma_bf16(sacc[2 * np],     al, bh[0], bh[1]);
                mma_bf16(sacc[2 * np + 1], ah, bh[2], bh[3]);
                mma_bf16(sacc[2 * np + 1], ah, bl[2], bl[3]);
                mma_bf16(sacc[2 * np + 1], al, bh[2], bh[3]);
            }
        }

        // ---- Mask + scale + online softmax ----
        float mx0 = -1e30f, mx1 = -1e30f;
#pragma unroll
        for (int j = 0; j < 8; ++j) {
            int col0 = 8 * j + c0l;
            int k0 = kb * 64 + col0, k1 = k0 + 1;
            int v0 = vflag[col0], v1 = vflag[col0 + 1];
            float s0 = (v0 && k0 <= qg0) ? sacc[j][0] * scale : -1e30f;
            float s1 = (v1 && k1 <= qg0) ? sacc[j][1] * scale : -1e30f;
            float s2 = (v0 && k0 <= qg1) ? sacc[j][2] * scale : -1e30f;
            float s3 = (v1 && k1 <= qg1) ? sacc[j][3] * scale : -1e30f;
            sacc[j][0] = s0; sacc[j][1] = s1; sacc[j][2] = s2; sacc[j][3] = s3;
            mx0 = fmaxf(mx0, fmaxf(s0, s1));
            mx1 = fmaxf(mx1, fmaxf(s2, s3));
        }
        mx0 = fmaxf(mx0, __shfl_xor_sync(0xffffffffu, mx0, 1));
        mx0 = fmaxf(mx0, __shfl_xor_sync(0xffffffffu, mx0, 2));
        mx1 = fmaxf(mx1, __shfl_xor_sync(0xffffffffu, mx1, 1));
        mx1 = fmaxf(mx1, __shfl_xor_sync(0xffffffffu, mx1, 2));

        float mn0 = fmaxf(m0, mx0), mn1 = fmaxf(m1, mx1);
        float al0 = __expf(m0 - mn0), al1 = __expf(m1 - mn1);
        m0 = mn0; m1 = mn1;

        float rs0 = 0.f, rs1 = 0.f;
#pragma unroll
        for (int j = 0; j < 8; ++j) {
            sacc[j][0] = __expf(sacc[j][0] - mn0);
            sacc[j][1] = __expf(sacc[j][1] - mn0);
            sacc[j][2] = __expf(sacc[j][2] - mn1);
            sacc[j][3] = __expf(sacc[j][3] - mn1);
            rs0 += sacc[j][0] + sacc[j][1];
            rs1 += sacc[j][2] + sacc[j][3];
        }
        rs0 += __shfl_xor_sync(0xffffffffu, rs0, 1);
        rs0 += __shfl_xor_sync(0xffffffffu, rs0, 2);
        rs1 += __shfl_xor_sync(0xffffffffu, rs1, 1);
        rs1 += __shfl_xor_sync(0xffffffffu, rs1, 2);
        l0 = l0 * al0 + rs0;
        l1 = l1 * al1 + rs1;
#pragma unroll
        for (int j = 0; j < 8; ++j) {
            oacc[j][0] *= al0; oacc[j][1] *= al0;
            oacc[j][2] *= al1; oacc[j][3] *= al1;
        }

        // ---- O += P V (3-pass hi/lo; P from S frags) ----
#pragma unroll
        for (int kt = 0; kt < 4; ++kt) {
            uint32_t ph[4], pl[4];
            cvt_hilo(sacc[2 * kt][0],     sacc[2 * kt][1],     ph[0], pl[0]);
            cvt_hilo(sacc[2 * kt][2],     sacc[2 * kt][3],     ph[1], pl[1]);
            cvt_hilo(sacc[2 * kt + 1][0], sacc[2 * kt + 1][1], ph[2], pl[2]);
            cvt_hilo(sacc[2 * kt + 1][2], sacc[2 * kt + 1][3], ph[3], pl[3]);
#pragma unroll
            for (int j2 = 0; j2 < 4; ++j2) {
                uint32_t vrow = (uint32_t)(kt * 16) + v_rowH;
                uint32_t vofs = vrow * 128 +
                    (((uint32_t)(j2 * 32) + v_colH) ^ v_xor);
                uint32_t vh[4], vl[4];
                ldsm4t(vh, sb + A_VHI + vofs);
                ldsm4t(vl, sb + A_VLO + vofs);
                mma_bf16(oacc[2 * j2],     ph, vh[0], vh[1]);
                mma_bf16(oacc[2 * j2],     ph, vl[0], vl[1]);
                mma_bf16(oacc[2 * j2],     pl, vh[0], vh[1]);
                mma_bf16(oacc[2 * j2 + 1], ph, vh[2], vh[3]);
                mma_bf16(oacc[2 * j2 + 1], ph, vl[2], vl[3]);
                mma_bf16(oacc[2 * j2 + 1], pl, vh[2], vh[3]);
            }
        }
    }

    // ---- Epilogue ----
    float inv0 = 1.f / l0, inv1 = 1.f / l1;
    const size_t row0 = (size_t)b * TT + qb * 128 + wq + r;
#pragma unroll
    for (int j = 0; j < 8; ++j) {
        int col = h * DD + 8 * j + c0l;
        float2 v0 = { oacc[j][0] * inv0, oacc[j][1] * inv0 };
        float2 v1 = { oacc[j][2] * inv1, oacc[j][3] * inv1 };
        *(float2*)(out + row0 * CC + col) = v0;
        *(float2*)(out + (row0 + 8) * CC + col) = v1;
    }
}

// ---------------------------------------------------------------------------
// Launch
// ---------------------------------------------------------------------------
extern "C" void kernel_launch(void* const* d_in, const int* in_sizes, int n_in,
                              void* d_out, int out_size) {
    const float*         x     = (const float*)d_in[0];
    const unsigned char* mask  = (const unsigned char*)d_in[1];
    const float*         Wqkv  = (const float*)d_in[2];
    const float*         bqkv  = (const float*)d_in[3];
    const float*         Wproj = (const float*)d_in[4];
    const float*         bproj = (const float*)d_in[5];
    float*               out   = (float*)d_out;

    float* qkv_ptr;  cudaGetSymbolAddress((void**)&qkv_ptr,  g_qkv);
    float* attn_ptr; cudaGetSymbolAddress((void**)&attn_ptr, g_attn);
    __nv_bfloat16 *xhi, *xlo, *wqh, *wql, *wph, *wpl, *ahi, *alo;
    cudaGetSymbolAddress((void**)&xhi, g_xhi);
    cudaGetSymbolAddress((void**)&xlo, g_xlo);
    cudaGetSymbolAddress((void**)&wqh, g_wqkvhi);
    cudaGetSymbolAddress((void**)&wql, g_wqkvlo);
    cudaGetSymbolAddress((void**)&wph, g_wprojhi);
    cudaGetSymbolAddress((void**)&wpl, g_wprojlo);
    cudaGetSymbolAddress((void**)&ahi, g_ahi);
    cudaGetSymbolAddress((void**)&alo, g_alo);

    // 1. mask
    {
        int n = BB * TT;
        mask_convert_kernel<<<(n + 255) / 256, 256>>>(mask, n);
    }

    // 2. splits
    {
        int n4 = MM * CC / 4;
        split_kernel<<<(n4 + 255) / 256, 256>>>(x, xhi, xlo, n4);
        n4 = 3 * CC * CC / 4;
        split_kernel<<<(n4 + 255) / 256, 256>>>(Wqkv, wqh, wql, n4);
        n4 = CC * CC / 4;
        split_kernel<<<(n4 + 255) / 256, 256>>>(Wproj, wph, wpl, n4);
    }

    cudaFuncSetAttribute(gemm_mma_kernel,
                         cudaFuncAttributeMaxDynamicSharedMemorySize,
                         GEMM_SMEM_DYN);

    // 3. QKV projection (HMMA)
    {
        dim3 grid(3 * CC / 128, MM / 128);
        gemm_mma_kernel<<<grid, 256, GEMM_SMEM_DYN>>>(xhi, xlo, wqh, wql,
                                                      bqkv, qkv_ptr, 3 * CC);
    }

    // 4. Attention (HMMA flash)
    {
        cudaFuncSetAttribute(attn_mma_kernel,
                             cudaFuncAttributeMaxDynamicSharedMemorySize,
                             ATTN2_SMEM);
        dim3 grid(TT / 128, HH, BB);
        attn_mma_kernel<<<grid, 256, ATTN2_SMEM>>>(attn_ptr);
    }

    // 5. split attention output
    {
        int n4 = MM * CC / 4;
        split_kernel<<<(n4 + 255) / 256, 256>>>(attn_ptr, ahi, alo, n4);
    }

    // 6. Output projection (HMMA)
    {
        dim3 grid(CC / 128, MM / 128);
        gemm_mma_kernel<<<grid, 256, GEMM_SMEM_DYN>>>(ahi, alo, wph, wpl,
                                                      bproj, out, CC);
    }
}

// round 6
// speedup vs baseline: 3.3274x; 1.6660x over previous
#include <cuda_runtime.h>
#include <cuda_fp16.h>
#include <cstdint>

// Problem constants
#define BB 2
#define TT 2048
#define CC 1024
#define HH 16
#define DD 64
#define MM (BB * TT)          // 4096 rows

// ---------------------------------------------------------------------------
// Scratch (__device__ globals; allocation-free rule)
// ---------------------------------------------------------------------------
__device__ int    g_valid[BB * TT];
__device__ __half g_xhi[(size_t)MM * CC];
__device__ __half g_xlo[(size_t)MM * CC];
__device__ __half g_wqh[(size_t)3 * CC * CC];
__device__ __half g_wql[(size_t)3 * CC * CC];
__device__ __half g_wph[(size_t)CC * CC];
__device__ __half g_qkvh[(size_t)MM * 3 * CC];   // (B,T,3C) fp16 hi plane
__device__ __half g_qkvl[(size_t)MM * 3 * CC];   // lo plane
__device__ __half g_ah[(size_t)MM * CC];         // attention out hi
__device__ __half g_al[(size_t)MM * CC];         // attention out lo

// ---------------------------------------------------------------------------
// PTX helpers (baseline features only: valid for compute_103)
// ---------------------------------------------------------------------------
__device__ __forceinline__ uint32_t smem_u32(const void* p) {
    uint32_t a;
    asm("{ .reg .u64 t; cvta.to.shared.u64 t, %1; cvt.u32.u64 %0, t; }"
        : "=r"(a) : "l"(p));
    return a;
}

__device__ __forceinline__ void cp16(uint32_t dst, const void* src) {
    asm volatile("cp.async.cg.shared.global [%0], [%1], 16;"
                 :: "r"(dst), "l"(src) : "memory");
}
__device__ __forceinline__ void cp_commit() {
    asm volatile("cp.async.commit_group;" ::: "memory");
}
template <int N>
__device__ __forceinline__ void cp_wait() {
    asm volatile("cp.async.wait_group %0;" :: "n"(N) : "memory");
}

__device__ __forceinline__ void ldsm4(uint32_t r[4], uint32_t addr) {
    asm volatile("ldmatrix.sync.aligned.m8n8.x4.shared.b16 {%0,%1,%2,%3}, [%4];"
                 : "=r"(r[0]), "=r"(r[1]), "=r"(r[2]), "=r"(r[3]) : "r"(addr));
}

__device__ __forceinline__ void ldsm4t(uint32_t r[4], uint32_t addr) {
    asm volatile("ldmatrix.sync.aligned.m8n8.x4.trans.shared.b16 {%0,%1,%2,%3}, [%4];"
                 : "=r"(r[0]), "=r"(r[1]), "=r"(r[2]), "=r"(r[3]) : "r"(addr));
}

__device__ __forceinline__ void mma_f16(float c[4],
                                        const uint32_t a[4],
                                        uint32_t b0, uint32_t b1) {
    asm volatile(
        "mma.sync.aligned.m16n8k16.row.col.f32.f16.f16.f32 "
        "{%0,%1,%2,%3}, {%4,%5,%6,%7}, {%8,%9}, {%0,%1,%2,%3};"
        : "+f"(c[0]), "+f"(c[1]), "+f"(c[2]), "+f"(c[3])
        : "r"(a[0]), "r"(a[1]), "r"(a[2]), "r"(a[3]), "r"(b0), "r"(b1));
}

// Pack two fp32 into fp16x2 hi plane + fp16x2 residual lo plane.
__device__ __forceinline__ void cvt_hilo(float e0, float e1,
                                         uint32_t& hi, uint32_t& lo) {
    __half h0 = __float2half_rn(e0);
    __half h1 = __float2half_rn(e1);
    float r0 = e0 - __half2float(h0);
    float r1 = e1 - __half2float(h1);
    __half g0 = __float2half_rn(r0);
    __half g1 = __float2half_rn(r1);
    hi = ((uint32_t)__half_as_ushort(h1) << 16) | (uint32_t)__half_as_ushort(h0);
    lo = ((uint32_t)__half_as_ushort(g1) << 16) | (uint32_t)__half_as_ushort(g0);
}

__device__ __forceinline__ uint32_t cvt_hi2(float e0, float e1) {
    __half h0 = __float2half_rn(e0);
    __half h1 = __float2half_rn(e1);
    return ((uint32_t)__half_as_ushort(h1) << 16) | (uint32_t)__half_as_ushort(h0);
}

// ---------------------------------------------------------------------------
// Mask normalization (uint8 vs 4-byte storage detection)
// ---------------------------------------------------------------------------
__global__ void mask_convert_kernel(const unsigned char* __restrict__ raw, int n) {
    int i = blockIdx.x * blockDim.x + threadIdx.x;
    if (i >= n) return;
    bool one_byte = (raw[1] != 0);
    int v = one_byte ? (raw[i] != 0) : (((const unsigned int*)raw)[i] != 0u);
    g_valid[i] = v;
}

// ---------------------------------------------------------------------------
// fp32 -> fp16 splits
// ---------------------------------------------------------------------------
__global__ void split2_kernel(const float* __restrict__ in,
                              __half* __restrict__ hi,
                              __half* __restrict__ lo, int n4) {
    int i = blockIdx.x * blockDim.x + threadIdx.x;
    if (i >= n4) return;
    float4 v = ((const float4*)in)[i];
    uint32_t h0, l0, h1, l1;
    cvt_hilo(v.x, v.y, h0, l0);
    cvt_hilo(v.z, v.w, h1, l1);
    ((uint2*)hi)[i] = make_uint2(h0, h1);
    ((uint2*)lo)[i] = make_uint2(l0, l1);
}

__global__ void split1_kernel(const float* __restrict__ in,
                              __half* __restrict__ hi, int n4) {
    int i = blockIdx.x * blockDim.x + threadIdx.x;
    if (i >= n4) return;
    float4 v = ((const float4*)in)[i];
    ((uint2*)hi)[i] = make_uint2(cvt_hi2(v.x, v.y), cvt_hi2(v.z, v.w));
}

// ---------------------------------------------------------------------------
// HMMA GEMM (NT): C[M][N] = A[M][K] * W[N][K]^T + bias.
// PASSES=3: (Ah*Wh + Ah*Wl + Al*Wh).  PASSES=2: (Ah+Al)*Wh (W lo unused).
// SPLIT_OUT=1: write fp16 hi/lo planes.  SPLIT_OUT=0: write fp32.
// CTA tile 128x128, 8 warps (2M x 4N), mma m16n8k16, K-chunk 64 (128B SW128),
// cp.async double buffer.
// ---------------------------------------------------------------------------
__device__ __forceinline__ void stage_cp(const __half* __restrict__ g,
                                         uint32_t sm_dst, int row0,
                                         int k_byte0, int tid) {
#pragma unroll
    for (int u = 0; u < 4; ++u) {
        int s = u * 256 + tid;
        int row = s >> 3, seg = s & 7;
        const char* src = (const char*)g +
            (size_t)(row0 + row) * (CC * 2) + k_byte0 + seg * 16;
        uint32_t off = (uint32_t)(row * 128 + seg * 16);
        uint32_t sw = off ^ ((off >> 3) & 0x70);
        cp16(sm_dst + sw, src);
    }
}

template<int PASSES, int SPLIT_OUT>
__global__ __launch_bounds__(256) void gemm_mma_kernel(
    const __half* __restrict__ Ahi, const __half* __restrict__ Alo,
    const __half* __restrict__ Whi, const __half* __restrict__ Wlo,
    const float* __restrict__ bias,
    float* __restrict__ out, __half* __restrict__ outh, __half* __restrict__ outl,
    int N)
{
    constexpr uint32_t STAGE = (PASSES == 3) ? 65536u : 49152u;
    extern __shared__ char dynsmem[];
    const int tid  = threadIdx.x;
    const int wid  = tid >> 5;
    const int lane = tid & 31;
    const int m0 = blockIdx.y * 128;
    const int n0 = blockIdx.x * 128;
    const int wm = (wid >> 2) * 64;
    const int wn = (wid & 3) * 32;

    uint32_t base = smem_u32(dynsmem);
    base = (base + 1023u) & ~1023u;

    float acc[4][4][4];
#pragma unroll
    for (int mt = 0; mt < 4; ++mt)
#pragma unroll
        for (int nt = 0; nt < 4; ++nt)
#pragma unroll
            for (int r = 0; r < 4; ++r) acc[mt][nt][r] = 0.f;

    const int sub = lane >> 3;
    const int lr  = lane & 7;
    int arow[4];  uint32_t axor[4];
#pragma unroll
    for (int mt = 0; mt < 4; ++mt) {
        arow[mt] = wm + mt * 16 + (sub & 1) * 8 + lr;
        axor[mt] = (uint32_t)((arow[mt] & 7) << 4);
    }
    const uint32_t acolH = (uint32_t)((sub >> 1) * 16);
    int brow[2];  uint32_t bxor[2];
#pragma unroll
    for (int np = 0; np < 2; ++np) {
        brow[np] = wn + np * 16 + (sub >> 1) * 8 + lr;
        bxor[np] = (uint32_t)((brow[np] & 7) << 4);
    }
    const uint32_t bcolH = (uint32_t)((sub & 1) * 16);

    const int NC = CC / 64;

    {
        uint32_t sb = base;
        stage_cp(Ahi, sb,          m0, 0, tid);
        stage_cp(Alo, sb + 16384,  m0, 0, tid);
        stage_cp(Whi, sb + 32768,  n0, 0, tid);
        if (PASSES == 3) stage_cp(Wlo, sb + 49152, n0, 0, tid);
        cp_commit();
    }

    for (int c = 0; c < NC; ++c) {
        if (c + 1 < NC) {
            uint32_t sb = base + (uint32_t)((c + 1) & 1) * STAGE;
            int kb = (c + 1) * 128;
            stage_cp(Ahi, sb,          m0, kb, tid);
            stage_cp(Alo, sb + 16384,  m0, kb, tid);
            stage_cp(Whi, sb + 32768,  n0, kb, tid);
            if (PASSES == 3) stage_cp(Wlo, sb + 49152, n0, kb, tid);
            cp_commit();
            cp_wait<1>();
        } else {
            cp_wait<0>();
        }
        __syncthreads();

        uint32_t sb  = base + (uint32_t)(c & 1) * STAGE;
        uint32_t aH = sb, aL = sb + 16384, bH = sb + 32768, bL = sb + 49152;

#pragma unroll
        for (int ks = 0; ks < 4; ++ks) {
            uint32_t kA = (uint32_t)(ks * 32) + acolH;
            uint32_t kB = (uint32_t)(ks * 32) + bcolH;
            uint32_t ah[4][4], al[4][4], bh[2][4], bl[2][4];
#pragma unroll
            for (int mt = 0; mt < 4; ++mt) {
                uint32_t rofs = (uint32_t)(arow[mt] * 128) + (kA ^ axor[mt]);
                ldsm4(ah[mt], aH + rofs);
                ldsm4(al[mt], aL + rofs);
            }
#pragma unroll
            for (int np = 0; np < 2; ++np) {
                uint32_t rofs = (uint32_t)(brow[np] * 128) + (kB ^ bxor[np]);
                ldsm4(bh[np], bH + rofs);
                if (PASSES == 3) ldsm4(bl[np], bL + rofs);
            }
#pragma unroll
            for (int mt = 0; mt < 4; ++mt)
#pragma unroll
                for (int nt = 0; nt < 4; ++nt) {
                    int np = nt >> 1, o = (nt & 1) * 2;
                    mma_f16(acc[mt][nt], ah[mt], bh[np][o], bh[np][o + 1]);
                    if (PASSES == 3)
                        mma_f16(acc[mt][nt], ah[mt], bl[np][o], bl[np][o + 1]);
                    mma_f16(acc[mt][nt], al[mt], bh[np][o], bh[np][o + 1]);
                }
        }
        __syncthreads();
    }

    const int erow = m0 + wm + (lane >> 2);
    const int ecol0 = n0 + wn + (lane & 3) * 2;
#pragma unroll
    for (int mt = 0; mt < 4; ++mt) {
#pragma unroll
        for (int nt = 0; nt < 4; ++nt) {
            int row = erow + mt * 16;
            int col = ecol0 + nt * 8;
            float b0 = bias[col], b1 = bias[col + 1];
            float a0 = acc[mt][nt][0] + b0, a1 = acc[mt][nt][1] + b1;
            float a2 = acc[mt][nt][2] + b0, a3 = acc[mt][nt][3] + b1;
            if (SPLIT_OUT) {
                uint32_t hi0, lo0, hi1, lo1;
                cvt_hilo(a0, a1, hi0, lo0);
                cvt_hilo(a2, a3, hi1, lo1);
                *(uint32_t*)(outh + (size_t)row * N + col) = hi0;
                *(uint32_t*)(outl + (size_t)row * N + col) = lo0;
                *(uint32_t*)(outh + (size_t)(row + 8) * N + col) = hi1;
                *(uint32_t*)(outl + (size_t)(row + 8) * N + col) = lo1;
            } else {
                *(float2*)(out + (size_t)row * N + col) = make_float2(a0, a1);
                *(float2*)(out + (size_t)(row + 8) * N + col) = make_float2(a2, a3);
            }
        }
    }
}

// ---------------------------------------------------------------------------
// HMMA flash attention (fp16 planes, cp.async, double-buffered KV).
// CTA: 128 queries x (b,h); 8 warps x 16 q rows (warp-local softmax).
// QK^T: 3-pass (Qh*Kh + Qh*Kl + Ql*Kh).  PV: 2-pass ((Ph+Pl)*Vh).
// smem: Qh 16K, Ql 16K, 2 x (Kh 8K + Kl 8K + Vh 8K) = 80KB.
// Output written directly as fp16 hi/lo planes (g_ah/g_al).
// ---------------------------------------------------------------------------
#define AT_QH 0
#define AT_QL 16384
#define AT_KV 32768
#define AT_BUF 24576
#define ATTN_DYN (32768 + 2 * 24576 + 1024)

__global__ __launch_bounds__(256) void attn_mma_kernel() {
    extern __shared__ char asmem[];
    __shared__ int vflag[64];

    uint32_t sb = smem_u32(asmem);
    sb = (sb + 1023u) & ~1023u;

    const int tid  = threadIdx.x;
    const int wid  = tid >> 5;
    const int lane = tid & 31;
    const int qb = 15 - blockIdx.x;       // heavy tiles first
    const int h  = blockIdx.y;
    const int b  = blockIdx.z;
    const int wq = wid * 16;
    const int niter = 2 * qb + 2;

    // ---- Stage Q (both planes) + KV tile 0 via cp.async ----
    {
        const char* qh = (const char*)(g_qkvh + (size_t)(b * TT + qb * 128) * 3072 + h * 64);
        const char* ql = (const char*)(g_qkvl + (size_t)(b * TT + qb * 128) * 3072 + h * 64);
#pragma unroll
        for (int u = 0; u < 4; ++u) {
            int s = u * 256 + tid;
            int row = s >> 3, seg = s & 7;
            uint32_t off = (uint32_t)(row * 128 + ((seg * 16) ^ ((row & 7) << 4)));
            cp16(sb + AT_QH + off, qh + (size_t)row * 6144 + seg * 16);
            cp16(sb + AT_QL + off, ql + (size_t)row * 6144 + seg * 16);
        }
    }
    auto stage_kv = [&](int kbn, uint32_t bufb) {
        size_t rb = (size_t)(b * TT + kbn * 64) * 3072 + h * 64;
        const char* kh = (const char*)(g_qkvh + rb + 1024);
        const char* kl = (const char*)(g_qkvl + rb + 1024);
        const char* vh = (const char*)(g_qkvh + rb + 2048);
#pragma unroll
        for (int u = 0; u < 2; ++u) {
            int s = u * 256 + tid;
            int row = s >> 3, seg = s & 7;
            uint32_t off = (uint32_t)(row * 128 + ((seg * 16) ^ ((row & 7) << 4)));
            cp16(bufb + off,         kh + (size_t)row * 6144 + seg * 16);
            cp16(bufb + 8192 + off,  kl + (size_t)row * 6144 + seg * 16);
            cp16(bufb + 16384 + off, vh + (size_t)row * 6144 + seg * 16);
        }
    };
    stage_kv(0, sb + AT_KV);
    cp_commit();

    // Fragment bookkeeping
    const int sub = lane >> 3;
    const int lr  = lane & 7;
    const uint32_t a_row  = (uint32_t)(wq + ((sub & 1) << 3) + lr);
    const uint32_t a_colH = (uint32_t)((sub >> 1) << 4);
    const uint32_t a_xor  = (uint32_t)(lr << 4);
    const uint32_t b_rowH = (uint32_t)(((sub >> 1) << 3) + lr);
    const uint32_t b_colH = (uint32_t)((sub & 1) << 4);
    const int vt = lane >> 3, vlr = lane & 7;
    const uint32_t v_rowH = (uint32_t)(((vt & 1) << 3) + vlr);
    const uint32_t v_colH = (uint32_t)((vt >> 1) << 4);
    const uint32_t v_xor  = (uint32_t)(vlr << 4);

    const int r   = lane >> 2;
    const int c0l = (lane & 3) * 2;
    const int qg0 = qb * 128 + wq + r;
    const int qg1 = qg0 + 8;
    const float scale = 0.125f;

    float oacc[8][4];
#pragma unroll
    for (int j = 0; j < 8; ++j)
#pragma unroll
        for (int e = 0; e < 4; ++e) oacc[j][e] = 0.f;
    float m0 = -1e30f, m1 = -1e30f, l0 = 0.f, l1 = 0.f;

    for (int kb = 0; kb < niter; ++kb) {
        int my = (tid < 64) ? g_valid[b * TT + kb * 64 + tid] : 0;
        int any = __syncthreads_or(my);   // also: all warps done with buf[(kb+1)&1]
        if (tid < 64) vflag[tid] = my;

        if (kb + 1 < niter) {
            stage_kv(kb + 1, sb + AT_KV + (uint32_t)((kb + 1) & 1) * AT_BUF);
            cp_commit();
            cp_wait<1>();
        } else {
            cp_wait<0>();
        }
        __syncthreads();
        if (!any) continue;

        uint32_t kvb = sb + AT_KV + (uint32_t)(kb & 1) * AT_BUF;
        uint32_t kH = kvb, kL = kvb + 8192, vH = kvb + 16384;

        // ---- S = Q K^T (3-pass) ----
        float sacc[8][4];
#pragma unroll
        for (int j = 0; j < 8; ++j)
#pragma unroll
            for (int e = 0; e < 4; ++e) sacc[j][e] = 0.f;

#pragma unroll
        for (int kt = 0; kt < 4; ++kt) {
            uint32_t aofs = a_row * 128 + (((uint32_t)(kt * 32) + a_colH) ^ a_xor);
            uint32_t ah[4], al[4];
            ldsm4(ah, sb + AT_QH + aofs);
            ldsm4(al, sb + AT_QL + aofs);
#pragma unroll
            for (int np = 0; np < 4; ++np) {
                uint32_t brow = (uint32_t)(np * 16) + b_rowH;
                uint32_t bofs = brow * 128 +
                    (((uint32_t)(kt * 32) + b_colH) ^ ((brow & 7) << 4));
                uint32_t bh[4], bl[4];
                ldsm4(bh, kH + bofs);
                ldsm4(bl, kL + bofs);
                mma_f16(sacc[2 * np],     ah, bh[0], bh[1]);
                mma_f16(sacc[2 * np],     ah, bl[0], bl[1]);
                mma_f16(sacc[2 * np],     al, bh[0], bh[1]);
                mma_f16(sacc[2 * np + 1], ah, bh[2], bh[3]);
                mma_f16(sacc[2 * np + 1], ah, bl[2], bl[3]);
                mma_f16(sacc[2 * np + 1], al, bh[2], bh[3]);
            }
        }

        // ---- Mask + scale + online softmax ----
        float mx0 = -1e30f, mx1 = -1e30f;
#pragma unroll
        for (int j = 0; j < 8; ++j) {
            int col0 = 8 * j + c0l;
            int k0 = kb * 64 + col0, k1 = k0 + 1;
            int v0 = vflag[col0], v1 = vflag[col0 + 1];
            float s0 = (v0 && k0 <= qg0) ? sacc[j][0] * scale : -1e30f;
            float s1 = (v1 && k1 <= qg0) ? sacc[j][1] * scale : -1e30f;
            float s2 = (v0 && k0 <= qg1) ? sacc[j][2] * scale : -1e30f;
            float s3 = (v1 && k1 <= qg1) ? sacc[j][3] * scale : -1e30f;
            sacc[j][0] = s0; sacc[j][1] = s1; sacc[j][2] = s2; sacc[j][3] = s3;
            mx0 = fmaxf(mx0, fmaxf(s0, s1));
            mx1 = fmaxf(mx1, fmaxf(s2, s3));
        }
        mx0 = fmaxf(mx0, __shfl_xor_sync(0xffffffffu, mx0, 1));
        mx0 = fmaxf(mx0, __shfl_xor_sync(0xffffffffu, mx0, 2));
        mx1 = fmaxf(mx1, __shfl_xor_sync(0xffffffffu, mx1, 1));
        mx1 = fmaxf(mx1, __shfl_xor_sync(0xffffffffu, mx1, 2));

        float mn0 = fmaxf(m0, mx0), mn1 = fmaxf(m1, mx1);
        float al0 = __expf(m0 - mn0), al1 = __expf(m1 - mn1);
        m0 = mn0; m1 = mn1;

        float rs0 = 0.f, rs1 = 0.f;
#pragma unroll
        for (int j = 0; j < 8; ++j) {
            sacc[j][0] = __expf(sacc[j][0] - mn0);
            sacc[j][1] = __expf(sacc[j][1] - mn0);
            sacc[j][2] = __expf(sacc[j][2] - mn1);
            sacc[j][3] = __expf(sacc[j][3] - mn1);
            rs0 += sacc[j][0] + sacc[j][1];
            rs1 += sacc[j][2] + sacc[j][3];
        }
        rs0 += __shfl_xor_sync(0xffffffffu, rs0, 1);
        rs0 += __shfl_xor_sync(0xffffffffu, rs0, 2);
        rs1 += __shfl_xor_sync(0xffffffffu, rs1, 1);
        rs1 += __shfl_xor_sync(0xffffffffu, rs1, 2);
        l0 = l0 * al0 + rs0;
        l1 = l1 * al1 + rs1;
#pragma unroll
        for (int j = 0; j < 8; ++j) {
            oacc[j][0] *= al0; oacc[j][1] *= al0;
            oacc[j][2] *= al1; oacc[j][3] *= al1;
        }

        // ---- O += P V (2-pass: (Ph+Pl) * Vh) ----
#pragma unroll
        for (int kt = 0; kt < 4; ++kt) {
            uint32_t ph[4], pl[4];
            cvt_hilo(sacc[2 * kt][0],     sacc[2 * kt][1],     ph[0], pl[0]);
            cvt_hilo(sacc[2 * kt][2],     sacc[2 * kt][3],     ph[1], pl[1]);
            cvt_hilo(sacc[2 * kt + 1][0], sacc[2 * kt + 1][1], ph[2], pl[2]);
            cvt_hilo(sacc[2 * kt + 1][2], sacc[2 * kt + 1][3], ph[3], pl[3]);
#pragma unroll
            for (int j2 = 0; j2 < 4; ++j2) {
                uint32_t vrow = (uint32_t)(kt * 16) + v_rowH;
                uint32_t vofs = vrow * 128 +
                    (((uint32_t)(j2 * 32) + v_colH) ^ v_xor);
                uint32_t vh[4];
                ldsm4t(vh, vH + vofs);
                mma_f16(oacc[2 * j2],     ph, vh[0], vh[1]);
                mma_f16(oacc[2 * j2],     pl, vh[0], vh[1]);
                mma_f16(oacc[2 * j2 + 1], ph, vh[2], vh[3]);
                mma_f16(oacc[2 * j2 + 1], pl, vh[2], vh[3]);
            }
        }
    }

    // ---- Epilogue: write hi/lo fp16 planes for GEMM2 ----
    float inv0 = 1.f / l0, inv1 = 1.f / l1;
    const size_t row0 = (size_t)b * TT + qb * 128 + wq + r;
#pragma unroll
    for (int j = 0; j < 8; ++j) {
        int col = h * DD + 8 * j + c0l;
        uint32_t hi0, lo0, hi1, lo1;
        cvt_hilo(oacc[j][0] * inv0, oacc[j][1] * inv0, hi0, lo0);
        cvt_hilo(oacc[j][2] * inv1, oacc[j][3] * inv1, hi1, lo1);
        *(uint32_t*)(g_ah + row0 * CC + col) = hi0;
        *(uint32_t*)(g_al + row0 * CC + col) = lo0;
        *(uint32_t*)(g_ah + (row0 + 8) * CC + col) = hi1;
        *(uint32_t*)(g_al + (row0 + 8) * CC + col) = lo1;
    }
}

// ---------------------------------------------------------------------------
// Launch
// ---------------------------------------------------------------------------
extern "C" void kernel_launch(void* const* d_in, const int* in_sizes, int n_in,
                              void* d_out, int out_size) {
    const float*         x     = (const float*)d_in[0];
    const unsigned char* mask  = (const unsigned char*)d_in[1];
    const float*         Wqkv  = (const float*)d_in[2];
    const float*         bqkv  = (const float*)d_in[3];
    const float*         Wproj = (const float*)d_in[4];
    const float*         bproj = (const float*)d_in[5];
    float*               out   = (float*)d_out;

    __half *xhi, *xlo, *wqh, *wql, *wph, *qkvh, *qkvl, *ahi, *alo;
    cudaGetSymbolAddress((void**)&xhi,  g_xhi);
    cudaGetSymbolAddress((void**)&xlo,  g_xlo);
    cudaGetSymbolAddress((void**)&wqh,  g_wqh);
    cudaGetSymbolAddress((void**)&wql,  g_wql);
    cudaGetSymbolAddress((void**)&wph,  g_wph);
    cudaGetSymbolAddress((void**)&qkvh, g_qkvh);
    cudaGetSymbolAddress((void**)&qkvl, g_qkvl);
    cudaGetSymbolAddress((void**)&ahi,  g_ah);
    cudaGetSymbolAddress((void**)&alo,  g_al);

    // 1. mask
    {
        int n = BB * TT;
        mask_convert_kernel<<<(n + 255) / 256, 256>>>(mask, n);
    }

    // 2. splits: x (hi+lo), Wqkv (hi+lo), Wproj (hi only)
    {
        int n4 = MM * CC / 4;
        split2_kernel<<<(n4 + 255) / 256, 256>>>(x, xhi, xlo, n4);
        n4 = 3 * CC * CC / 4;
        split2_kernel<<<(n4 + 255) / 256, 256>>>(Wqkv, wqh, wql, n4);
        n4 = CC * CC / 4;
        split1_kernel<<<(n4 + 255) / 256, 256>>>(Wproj, wph, n4);
    }

    // 3. QKV projection: 3-pass, fp16 hi/lo output planes
    {
        const int dyn = 2 * 65536 + 1024;
        cudaFuncSetAttribute(gemm_mma_kernel<3, 1>,
                             cudaFuncAttributeMaxDynamicSharedMemorySize, dyn);
        dim3 grid(3 * CC / 128, MM / 128);
        gemm_mma_kernel<3, 1><<<grid, 256, dyn>>>(
            xhi, xlo, wqh, wql, bqkv, nullptr, qkvh, qkvl, 3 * CC);
    }

    // 4. Attention (fp16 planes in/out)
    {
        cudaFuncSetAttribute(attn_mma_kernel,
                             cudaFuncAttributeMaxDynamicSharedMemorySize,
                             ATTN_DYN);
        dim3 grid(TT / 128, HH, BB);
        attn_mma_kernel<<<grid, 256, ATTN_DYN>>>();
    }

    // 5. Output projection: 2-pass, fp32 output
    {
        const int dyn = 2 * 49152 + 1024;
        cudaFuncSetAttribute(gemm_mma_kernel<2, 0>,
                             cudaFuncAttributeMaxDynamicSharedMemorySize, dyn);
        dim3 grid(CC / 128, MM / 128);
        gemm_mma_kernel<2, 0><<<grid, 256, dyn>>>(
            ahi, alo, wph, wph, bproj, out, nullptr, nullptr, CC);
    }
}

// round 7
// speedup vs baseline: 3.4505x; 1.0370x over previous
#include <cuda_runtime.h>
#include <cuda_fp16.h>
#include <cstdint>

// Problem constants
#define BB 2
#define TT 2048
#define CC 1024
#define HH 16
#define DD 64
#define MM (BB * TT)          // 4096 rows

// ---------------------------------------------------------------------------
// Scratch (__device__ globals; allocation-free rule)
// ---------------------------------------------------------------------------
__device__ int    g_valid[BB * TT];
__device__ __half g_xhi[(size_t)MM * CC];
__device__ __half g_xlo[(size_t)MM * CC];
__device__ __half g_wqh[(size_t)3 * CC * CC];
__device__ __half g_wql[(size_t)3 * CC * CC];
__device__ __half g_wph[(size_t)CC * CC];
__device__ __half g_qkvh[(size_t)MM * 3 * CC];   // (B,T,3C) fp16 hi plane
__device__ __half g_qkvl[(size_t)MM * 3 * CC];   // lo plane
__device__ __half g_ah[(size_t)MM * CC];         // attention out hi
__device__ __half g_al[(size_t)MM * CC];         // attention out lo

// ---------------------------------------------------------------------------
// PTX helpers (baseline features only: valid for compute_103)
// ---------------------------------------------------------------------------
__device__ __forceinline__ uint32_t smem_u32(const void* p) {
    uint32_t a;
    asm("{ .reg .u64 t; cvta.to.shared.u64 t, %1; cvt.u32.u64 %0, t; }"
        : "=r"(a) : "l"(p));
    return a;
}

__device__ __forceinline__ void cp16(uint32_t dst, const void* src) {
    asm volatile("cp.async.cg.shared.global [%0], [%1], 16;"
                 :: "r"(dst), "l"(src) : "memory");
}
__device__ __forceinline__ void cp_commit() {
    asm volatile("cp.async.commit_group;" ::: "memory");
}
template <int N>
__device__ __forceinline__ void cp_wait() {
    asm volatile("cp.async.wait_group %0;" :: "n"(N) : "memory");
}

__device__ __forceinline__ void ldsm4(uint32_t r[4], uint32_t addr) {
    asm volatile("ldmatrix.sync.aligned.m8n8.x4.shared.b16 {%0,%1,%2,%3}, [%4];"
                 : "=r"(r[0]), "=r"(r[1]), "=r"(r[2]), "=r"(r[3]) : "r"(addr));
}

__device__ __forceinline__ void ldsm4t(uint32_t r[4], uint32_t addr) {
    asm volatile("ldmatrix.sync.aligned.m8n8.x4.trans.shared.b16 {%0,%1,%2,%3}, [%4];"
                 : "=r"(r[0]), "=r"(r[1]), "=r"(r[2]), "=r"(r[3]) : "r"(addr));
}

__device__ __forceinline__ void mma_f16(float c[4],
                                        const uint32_t a[4],
                                        uint32_t b0, uint32_t b1) {
    asm volatile(
        "mma.sync.aligned.m16n8k16.row.col.f32.f16.f16.f32 "
        "{%0,%1,%2,%3}, {%4,%5,%6,%7}, {%8,%9}, {%0,%1,%2,%3};"
        : "+f"(c[0]), "+f"(c[1]), "+f"(c[2]), "+f"(c[3])
        : "r"(a[0]), "r"(a[1]), "r"(a[2]), "r"(a[3]), "r"(b0), "r"(b1));
}

// Pack two fp32 into fp16x2 hi plane + fp16x2 residual lo plane.
__device__ __forceinline__ void cvt_hilo(float e0, float e1,
                                         uint32_t& hi, uint32_t& lo) {
    __half h0 = __float2half_rn(e0);
    __half h1 = __float2half_rn(e1);
    float r0 = e0 - __half2float(h0);
    float r1 = e1 - __half2float(h1);
    __half g0 = __float2half_rn(r0);
    __half g1 = __float2half_rn(r1);
    hi = ((uint32_t)__half_as_ushort(h1) << 16) | (uint32_t)__half_as_ushort(h0);
    lo = ((uint32_t)__half_as_ushort(g1) << 16) | (uint32_t)__half_as_ushort(g0);
}

__device__ __forceinline__ uint32_t cvt_hi2(float e0, float e1) {
    __half h0 = __float2half_rn(e0);
    __half h1 = __float2half_rn(e1);
    return ((uint32_t)__half_as_ushort(h1) << 16) | (uint32_t)__half_as_ushort(h0);
}

// ---------------------------------------------------------------------------
// Mask normalization (uint8 vs 4-byte storage detection)
// ---------------------------------------------------------------------------
__global__ void mask_convert_kernel(const unsigned char* __restrict__ raw, int n) {
    int i = blockIdx.x * blockDim.x + threadIdx.x;
    if (i >= n) return;
    bool one_byte = (raw[1] != 0);
    int v = one_byte ? (raw[i] != 0) : (((const unsigned int*)raw)[i] != 0u);
    g_valid[i] = v;
}

// ---------------------------------------------------------------------------
// fp32 -> fp16 splits
// ---------------------------------------------------------------------------
__global__ void split2_kernel(const float* __restrict__ in,
                              __half* __restrict__ hi,
                              __half* __restrict__ lo, int n4) {
    int i = blockIdx.x * blockDim.x + threadIdx.x;
    if (i >= n4) return;
    float4 v = ((const float4*)in)[i];
    uint32_t h0, l0, h1, l1;
    cvt_hilo(v.x, v.y, h0, l0);
    cvt_hilo(v.z, v.w, h1, l1);
    ((uint2*)hi)[i] = make_uint2(h0, h1);
    ((uint2*)lo)[i] = make_uint2(l0, l1);
}

__global__ void split1_kernel(const float* __restrict__ in,
                              __half* __restrict__ hi, int n4) {
    int i = blockIdx.x * blockDim.x + threadIdx.x;
    if (i >= n4) return;
    float4 v = ((const float4*)in)[i];
    ((uint2*)hi)[i] = make_uint2(cvt_hi2(v.x, v.y), cvt_hi2(v.z, v.w));
}

// ---------------------------------------------------------------------------
// HMMA GEMM (NT): C[M][N] = A[M][K] * W[N][K]^T + bias.
// CTA tile 128x256, 8 warps (2M x 4N), warp tile 64x64, mma m16n8k16,
// K-chunk 64 (128B rows, SW128), cp.async double buffer.
// PASSES=3: Ah*Wh + Ah*Wl + Al*Wh   (Wl pass skipped when n0 >= wl_limit)
// PASSES=2: (Ah+Al)*Wh              (Wlo never touched)
// SPLIT_OUT=1: write fp16 hi/lo planes; 0: write fp32.
// smem stage: Ah(16K) Al(16K) Wh(32K) [Wl(32K)] = 64K / 96K per stage.
// ---------------------------------------------------------------------------
template<int ROWS>
__device__ __forceinline__ void stage_cp(const __half* __restrict__ g,
                                         uint32_t sm_dst, int row0,
                                         int k_byte0, int tid) {
#pragma unroll
    for (int u = 0; u < ROWS / 32; ++u) {
        int s = u * 256 + tid;
        int row = s >> 3, seg = s & 7;
        const char* src = (const char*)g +
            (size_t)(row0 + row) * (CC * 2) + k_byte0 + seg * 16;
        uint32_t off = (uint32_t)(row * 128 + seg * 16);
        uint32_t sw = off ^ ((off >> 3) & 0x70);
        cp16(sm_dst + sw, src);
    }
}

template<int PASSES, int SPLIT_OUT>
__global__ __launch_bounds__(256) void gemm_mma_kernel(
    const __half* __restrict__ Ahi, const __half* __restrict__ Alo,
    const __half* __restrict__ Whi, const __half* __restrict__ Wlo,
    const float* __restrict__ bias,
    float* __restrict__ out, __half* __restrict__ outh, __half* __restrict__ outl,
    int N, int wl_limit)
{
    constexpr uint32_t STAGE = (PASSES == 3) ? 98304u : 65536u;
    extern __shared__ char dynsmem[];
    const int tid  = threadIdx.x;
    const int wid  = tid >> 5;
    const int lane = tid & 31;
    const int m0 = blockIdx.y * 128;
    const int n0 = blockIdx.x * 256;
    const int wm = (wid >> 2) * 64;
    const int wn = (wid & 3) * 64;
    const bool use_wl = (PASSES == 3) && (n0 < wl_limit);

    uint32_t base = smem_u32(dynsmem);
    base = (base + 1023u) & ~1023u;

    float acc[4][8][4];
#pragma unroll
    for (int mt = 0; mt < 4; ++mt)
#pragma unroll
        for (int nt = 0; nt < 8; ++nt)
#pragma unroll
            for (int r = 0; r < 4; ++r) acc[mt][nt][r] = 0.f;

    const int sub = lane >> 3;
    const int lr  = lane & 7;
    int arow[4];  uint32_t axor[4];
#pragma unroll
    for (int mt = 0; mt < 4; ++mt) {
        arow[mt] = wm + mt * 16 + (sub & 1) * 8 + lr;
        axor[mt] = (uint32_t)((arow[mt] & 7) << 4);
    }
    const uint32_t acolH = (uint32_t)((sub >> 1) * 16);
    int brow[4];  uint32_t bxor[4];
#pragma unroll
    for (int np = 0; np < 4; ++np) {
        brow[np] = wn + np * 16 + (sub >> 1) * 8 + lr;
        bxor[np] = (uint32_t)((brow[np] & 7) << 4);
    }
    const uint32_t bcolH = (uint32_t)((sub & 1) * 16);

    const int NC = CC / 64;

    auto stage_all = [&](uint32_t sb, int kb) {
        stage_cp<128>(Ahi, sb,          m0, kb, tid);
        stage_cp<128>(Alo, sb + 16384,  m0, kb, tid);
        stage_cp<256>(Whi, sb + 32768,  n0, kb, tid);
        if (use_wl) stage_cp<256>(Wlo, sb + 65536, n0, kb, tid);
    };

    stage_all(base, 0);
    cp_commit();

    for (int c = 0; c < NC; ++c) {
        if (c + 1 < NC) {
            stage_all(base + (uint32_t)((c + 1) & 1) * STAGE, (c + 1) * 128);
            cp_commit();
            cp_wait<1>();
        } else {
            cp_wait<0>();
        }
        __syncthreads();

        uint32_t sb  = base + (uint32_t)(c & 1) * STAGE;
        uint32_t aH = sb, aL = sb + 16384, bH = sb + 32768, bL = sb + 65536;

#pragma unroll
        for (int ks = 0; ks < 4; ++ks) {
            uint32_t kA = (uint32_t)(ks * 32) + acolH;
            uint32_t kB = (uint32_t)(ks * 32) + bcolH;
            uint32_t ah[4][4], al[4][4];
#pragma unroll
            for (int mt = 0; mt < 4; ++mt) {
                uint32_t rofs = (uint32_t)(arow[mt] * 128) + (kA ^ axor[mt]);
                ldsm4(ah[mt], aH + rofs);
                ldsm4(al[mt], aL + rofs);
            }
#pragma unroll
            for (int np = 0; np < 4; ++np) {
                uint32_t rofs = (uint32_t)(brow[np] * 128) + (kB ^ bxor[np]);
                uint32_t bh[4], bl[4];
                ldsm4(bh, bH + rofs);
                if (use_wl) ldsm4(bl, bL + rofs);
#pragma unroll
                for (int mt = 0; mt < 4; ++mt) {
#pragma unroll
                    for (int half = 0; half < 2; ++half) {
                        int nt = np * 2 + half;
                        int o = half * 2;
                        mma_f16(acc[mt][nt], ah[mt], bh[o], bh[o + 1]);
                        if (use_wl)
                            mma_f16(acc[mt][nt], ah[mt], bl[o], bl[o + 1]);
                        mma_f16(acc[mt][nt], al[mt], bh[o], bh[o + 1]);
                    }
                }
            }
        }
        __syncthreads();
    }

    const int erow = m0 + wm + (lane >> 2);
    const int ecol0 = n0 + wn + (lane & 3) * 2;
#pragma unroll
    for (int mt = 0; mt < 4; ++mt) {
#pragma unroll
        for (int nt = 0; nt < 8; ++nt) {
            int row = erow + mt * 16;
            int col = ecol0 + nt * 8;
            float b0 = bias[col], b1 = bias[col + 1];
            float a0 = acc[mt][nt][0] + b0, a1 = acc[mt][nt][1] + b1;
            float a2 = acc[mt][nt][2] + b0, a3 = acc[mt][nt][3] + b1;
            if (SPLIT_OUT) {
                uint32_t hi0, lo0, hi1, lo1;
                cvt_hilo(a0, a1, hi0, lo0);
                cvt_hilo(a2, a3, hi1, lo1);
                *(uint32_t*)(outh + (size_t)row * N + col) = hi0;
                *(uint32_t*)(outl + (size_t)row * N + col) = lo0;
                *(uint32_t*)(outh + (size_t)(row + 8) * N + col) = hi1;
                *(uint32_t*)(outl + (size_t)(row + 8) * N + col) = lo1;
            } else {
                *(float2*)(out + (size_t)row * N + col) = make_float2(a0, a1);
                *(float2*)(out + (size_t)(row + 8) * N + col) = make_float2(a2, a3);
            }
        }
    }
}

// ---------------------------------------------------------------------------
// HMMA flash attention (fp16 planes, cp.async, double-buffered KV).
// (unchanged from Round 5 — validated)
// ---------------------------------------------------------------------------
#define AT_QH 0
#define AT_QL 16384
#define AT_KV 32768
#define AT_BUF 24576
#define ATTN_DYN (32768 + 2 * 24576 + 1024)

__global__ __launch_bounds__(256) void attn_mma_kernel() {
    extern __shared__ char asmem[];
    __shared__ int vflag[64];

    uint32_t sb = smem_u32(asmem);
    sb = (sb + 1023u) & ~1023u;

    const int tid  = threadIdx.x;
    const int wid  = tid >> 5;
    const int lane = tid & 31;
    const int qb = 15 - blockIdx.x;       // heavy tiles first
    const int h  = blockIdx.y;
    const int b  = blockIdx.z;
    const int wq = wid * 16;
    const int niter = 2 * qb + 2;

    {
        const char* qh = (const char*)(g_qkvh + (size_t)(b * TT + qb * 128) * 3072 + h * 64);
        const char* ql = (const char*)(g_qkvl + (size_t)(b * TT + qb * 128) * 3072 + h * 64);
#pragma unroll
        for (int u = 0; u < 4; ++u) {
            int s = u * 256 + tid;
            int row = s >> 3, seg = s & 7;
            uint32_t off = (uint32_t)(row * 128 + ((seg * 16) ^ ((row & 7) << 4)));
            cp16(sb + AT_QH + off, qh + (size_t)row * 6144 + seg * 16);
            cp16(sb + AT_QL + off, ql + (size_t)row * 6144 + seg * 16);
        }
    }
    auto stage_kv = [&](int kbn, uint32_t bufb) {
        size_t rb = (size_t)(b * TT + kbn * 64) * 3072 + h * 64;
        const char* kh = (const char*)(g_qkvh + rb + 1024);
        const char* kl = (const char*)(g_qkvl + rb + 1024);
        const char* vh = (const char*)(g_qkvh + rb + 2048);
#pragma unroll
        for (int u = 0; u < 2; ++u) {
            int s = u * 256 + tid;
            int row = s >> 3, seg = s & 7;
            uint32_t off = (uint32_t)(row * 128 + ((seg * 16) ^ ((row & 7) << 4)));
            cp16(bufb + off,         kh + (size_t)row * 6144 + seg * 16);
            cp16(bufb + 8192 + off,  kl + (size_t)row * 6144 + seg * 16);
            cp16(bufb + 16384 + off, vh + (size_t)row * 6144 + seg * 16);
        }
    };
    stage_kv(0, sb + AT_KV);
    cp_commit();

    const int sub = lane >> 3;
    const int lr  = lane & 7;
    const uint32_t a_row  = (uint32_t)(wq + ((sub & 1) << 3) + lr);
    const uint32_t a_colH = (uint32_t)((sub >> 1) << 4);
    const uint32_t a_xor  = (uint32_t)(lr << 4);
    const uint32_t b_rowH = (uint32_t)(((sub >> 1) << 3) + lr);
    const uint32_t b_colH = (uint32_t)((sub & 1) << 4);
    const int vt = lane >> 3, vlr = lane & 7;
    const uint32_t v_rowH = (uint32_t)(((vt & 1) << 3) + vlr);
    const uint32_t v_colH = (uint32_t)((vt >> 1) << 4);
    const uint32_t v_xor  = (uint32_t)(vlr << 4);

    const int r   = lane >> 2;
    const int c0l = (lane & 3) * 2;
    const int qg0 = qb * 128 + wq + r;
    const int qg1 = qg0 + 8;
    const float scale = 0.125f;

    float oacc[8][4];
#pragma unroll
    for (int j = 0; j < 8; ++j)
#pragma unroll
        for (int e = 0; e < 4; ++e) oacc[j][e] = 0.f;
    float m0 = -1e30f, m1 = -1e30f, l0 = 0.f, l1 = 0.f;

    for (int kb = 0; kb < niter; ++kb) {
        int my = (tid < 64) ? g_valid[b * TT + kb * 64 + tid] : 0;
        int any = __syncthreads_or(my);
        if (tid < 64) vflag[tid] = my;

        if (kb + 1 < niter) {
            stage_kv(kb + 1, sb + AT_KV + (uint32_t)((kb + 1) & 1) * AT_BUF);
            cp_commit();
            cp_wait<1>();
        } else {
            cp_wait<0>();
        }
        __syncthreads();
        if (!any) continue;

        uint32_t kvb = sb + AT_KV + (uint32_t)(kb & 1) * AT_BUF;
        uint32_t kH = kvb, kL = kvb + 8192, vH = kvb + 16384;

        float sacc[8][4];
#pragma unroll
        for (int j = 0; j < 8; ++j)
#pragma unroll
            for (int e = 0; e < 4; ++e) sacc[j][e] = 0.f;

#pragma unroll
        for (int kt = 0; kt < 4; ++kt) {
            uint32_t aofs = a_row * 128 + (((uint32_t)(kt * 32) + a_colH) ^ a_xor);
            uint32_t ah[4], al[4];
            ldsm4(ah, sb + AT_QH + aofs);
            ldsm4(al, sb + AT_QL + aofs);
#pragma unroll
            for (int np = 0; np < 4; ++np) {
                uint32_t brow = (uint32_t)(np * 16) + b_rowH;
                uint32_t bofs = brow * 128 +
                    (((uint32_t)(kt * 32) + b_colH) ^ ((brow & 7) << 4));
                uint32_t bh[4], bl[4];
                ldsm4(bh, kH + bofs);
                ldsm4(bl, kL + bofs);
                mma_f16(sacc[2 * np],     ah, bh[0], bh[1]);
                mma_f16(sacc[2 * np],     ah, bl[0], bl[1]);
                mma_f16(sacc[2 * np],     al, bh[0], bh[1]);
                mma_f16(sacc[2 * np + 1], ah, bh[2], bh[3]);
                mma_f16(sacc[2 * np + 1], ah, bl[2], bl[3]);
                mma_f16(sacc[2 * np + 1], al, bh[2], bh[3]);
            }
        }

        float mx0 = -1e30f, mx1 = -1e30f;
#pragma unroll
        for (int j = 0; j < 8; ++j) {
            int col0 = 8 * j + c0l;
            int k0 = kb * 64 + col0, k1 = k0 + 1;
            int v0 = vflag[col0], v1 = vflag[col0 + 1];
            float s0 = (v0 && k0 <= qg0) ? sacc[j][0] * scale : -1e30f;
            float s1 = (v1 && k1 <= qg0) ? sacc[j][1] * scale : -1e30f;
            float s2 = (v0 && k0 <= qg1) ? sacc[j][2] * scale : -1e30f;
            float s3 = (v1 && k1 <= qg1) ? sacc[j][3] * scale : -1e30f;
            sacc[j][0] = s0; sacc[j][1] = s1; sacc[j][2] = s2; sacc[j][3] = s3;
            mx0 = fmaxf(mx0, fmaxf(s0, s1));
            mx1 = fmaxf(mx1, fmaxf(s2, s3));
        }
        mx0 = fmaxf(mx0, __shfl_xor_sync(0xffffffffu, mx0, 1));
        mx0 = fmaxf(mx0, __shfl_xor_sync(0xffffffffu, mx0, 2));
        mx1 = fmaxf(mx1, __shfl_xor_sync(0xffffffffu, mx1, 1));
        mx1 = fmaxf(mx1, __shfl_xor_sync(0xffffffffu, mx1, 2));

        float mn0 = fmaxf(m0, mx0), mn1 = fmaxf(m1, mx1);
        float al0 = __expf(m0 - mn0), al1 = __expf(m1 - mn1);
        m0 = mn0; m1 = mn1;

        float rs0 = 0.f, rs1 = 0.f;
#pragma unroll
        for (int j = 0; j < 8; ++j) {
            sacc[j][0] = __expf(sacc[j][0] - mn0);
            sacc[j][1] = __expf(sacc[j][1] - mn0);
            sacc[j][2] = __expf(sacc[j][2] - mn1);
            sacc[j][3] = __expf(sacc[j][3] - mn1);
            rs0 += sacc[j][0] + sacc[j][1];
            rs1 += sacc[j][2] + sacc[j][3];
        }
        rs0 += __shfl_xor_sync(0xffffffffu, rs0, 1);
        rs0 += __shfl_xor_sync(0xffffffffu, rs0, 2);
        rs1 += __shfl_xor_sync(0xffffffffu, rs1, 1);
        rs1 += __shfl_xor_sync(0xffffffffu, rs1, 2);
        l0 = l0 * al0 + rs0;
        l1 = l1 * al1 + rs1;
#pragma unroll
        for (int j = 0; j < 8; ++j) {
            oacc[j][0] *= al0; oacc[j][1] *= al0;
            oacc[j][2] *= al1; oacc[j][3] *= al1;
        }

#pragma unroll
        for (int kt = 0; kt < 4; ++kt) {
            uint32_t ph[4], pl[4];
            cvt_hilo(sacc[2 * kt][0],     sacc[2 * kt][1],     ph[0], pl[0]);
            cvt_hilo(sacc[2 * kt][2],     sacc[2 * kt][3],     ph[1], pl[1]);
            cvt_hilo(sacc[2 * kt + 1][0], sacc[2 * kt + 1][1], ph[2], pl[2]);
            cvt_hilo(sacc[2 * kt + 1][2], sacc[2 * kt + 1][3], ph[3], pl[3]);
#pragma unroll
            for (int j2 = 0; j2 < 4; ++j2) {
                uint32_t vrow = (uint32_t)(kt * 16) + v_rowH;
                uint32_t vofs = vrow * 128 +
                    (((uint32_t)(j2 * 32) + v_colH) ^ v_xor);
                uint32_t vh[4];
                ldsm4t(vh, vH + vofs);
                mma_f16(oacc[2 * j2],     ph, vh[0], vh[1]);
                mma_f16(oacc[2 * j2],     pl, vh[0], vh[1]);
                mma_f16(oacc[2 * j2 + 1], ph, vh[2], vh[3]);
                mma_f16(oacc[2 * j2 + 1], pl, vh[2], vh[3]);
            }
        }
    }

    float inv0 = 1.f / l0, inv1 = 1.f / l1;
    const size_t row0 = (size_t)b * TT + qb * 128 + wq + r;
#pragma unroll
    for (int j = 0; j < 8; ++j) {
        int col = h * DD + 8 * j + c0l;
        uint32_t hi0, lo0, hi1, lo1;
        cvt_hilo(oacc[j][0] * inv0, oacc[j][1] * inv0, hi0, lo0);
        cvt_hilo(oacc[j][2] * inv1, oacc[j][3] * inv1, hi1, lo1);
        *(uint32_t*)(g_ah + row0 * CC + col) = hi0;
        *(uint32_t*)(g_al + row0 * CC + col) = lo0;
        *(uint32_t*)(g_ah + (row0 + 8) * CC + col) = hi1;
        *(uint32_t*)(g_al + (row0 + 8) * CC + col) = lo1;
    }
}

// ---------------------------------------------------------------------------
// Launch
// ---------------------------------------------------------------------------
extern "C" void kernel_launch(void* const* d_in, const int* in_sizes, int n_in,
                              void* d_out, int out_size) {
    const float*         x     = (const float*)d_in[0];
    const unsigned char* mask  = (const unsigned char*)d_in[1];
    const float*         Wqkv  = (const float*)d_in[2];
    const float*         bqkv  = (const float*)d_in[3];
    const float*         Wproj = (const float*)d_in[4];
    const float*         bproj = (const float*)d_in[5];
    float*               out   = (float*)d_out;

    __half *xhi, *xlo, *wqh, *wql, *wph, *qkvh, *qkvl, *ahi, *alo;
    cudaGetSymbolAddress((void**)&xhi,  g_xhi);
    cudaGetSymbolAddress((void**)&xlo,  g_xlo);
    cudaGetSymbolAddress((void**)&wqh,  g_wqh);
    cudaGetSymbolAddress((void**)&wql,  g_wql);
    cudaGetSymbolAddress((void**)&wph,  g_wph);
    cudaGetSymbolAddress((void**)&qkvh, g_qkvh);
    cudaGetSymbolAddress((void**)&qkvl, g_qkvl);
    cudaGetSymbolAddress((void**)&ahi,  g_ah);
    cudaGetSymbolAddress((void**)&alo,  g_al);

    // 1. mask
    {
        int n = BB * TT;
        mask_convert_kernel<<<(n + 255) / 256, 256>>>(mask, n);
    }

    // 2. splits: x (hi+lo), Wqkv (hi+lo), Wproj (hi only)
    {
        int n4 = MM * CC / 4;
        split2_kernel<<<(n4 + 255) / 256, 256>>>(x, xhi, xlo, n4);
        n4 = 3 * CC * CC / 4;
        split2_kernel<<<(n4 + 255) / 256, 256>>>(Wqkv, wqh, wql, n4);
        n4 = CC * CC / 4;
        split1_kernel<<<(n4 + 255) / 256, 256>>>(Wproj, wph, n4);
    }

    // 3. QKV projection: 3-pass (Q,K cols) / 2-pass (V cols), fp16 planes out
    {
        const int dyn = 2 * 98304 + 1024;
        cudaFuncSetAttribute(gemm_mma_kernel<3, 1>,
                             cudaFuncAttributeMaxDynamicSharedMemorySize, dyn);
        dim3 grid(3 * CC / 256, MM / 128);
        gemm_mma_kernel<3, 1><<<grid, 256, dyn>>>(
            xhi, xlo, wqh, wql, bqkv, nullptr, qkvh, qkvl, 3 * CC, 2 * CC);
    }

    // 4. Attention (fp16 planes in/out)
    {
        cudaFuncSetAttribute(attn_mma_kernel,
                             cudaFuncAttributeMaxDynamicSharedMemorySize,
                             ATTN_DYN);
        dim3 grid(TT / 128, HH, BB);
        attn_mma_kernel<<<grid, 256, ATTN_DYN>>>();
    }

    // 5. Output projection: 2-pass, fp32 output (single wave: 128 CTAs)
    {
        const int dyn = 2 * 65536 + 1024;
        cudaFuncSetAttribute(gemm_mma_kernel<2, 0>,
                             cudaFuncAttributeMaxDynamicSharedMemorySize, dyn);
        dim3 grid(CC / 256, MM / 128);
        gemm_mma_kernel<2, 0><<<grid, 256, dyn>>>(
            ahi, alo, wph, wph, bproj, out, nullptr, nullptr, CC, 0);
    }
}

// round 10
// speedup vs baseline: 3.4729x; 1.0065x over previous
#include <cuda_runtime.h>
#include <cuda_fp16.h>
#include <cstdint>

// Problem constants
#define BB 2
#define TT 2048
#define CC 1024
#define HH 16
#define DD 64
#define MM (BB * TT)          // 4096 rows

// ---------------------------------------------------------------------------
// Scratch (__device__ globals; allocation-free rule)
// ---------------------------------------------------------------------------
__device__ int    g_valid[BB * TT];
__device__ __half g_xhi[(size_t)MM * CC];
__device__ __half g_xlo[(size_t)MM * CC];
__device__ __half g_wqh[(size_t)3 * CC * CC];
__device__ __half g_wql[(size_t)3 * CC * CC];
__device__ __half g_wph[(size_t)CC * CC];
__device__ __half g_qkvh[(size_t)MM * 3 * CC];   // (B,T,3C) fp16 hi plane
__device__ __half g_qkvl[(size_t)MM * 3 * CC];   // lo plane
__device__ __half g_ah[(size_t)MM * CC];         // attention out hi
__device__ __half g_al[(size_t)MM * CC];         // attention out lo

// ---------------------------------------------------------------------------
// PTX helpers (baseline features only: valid for compute_103)
// ---------------------------------------------------------------------------
__device__ __forceinline__ uint32_t smem_u32(const void* p) {
    uint32_t a;
    asm("{ .reg .u64 t; cvta.to.shared.u64 t, %1; cvt.u32.u64 %0, t; }"
        : "=r"(a) : "l"(p));
    return a;
}

__device__ __forceinline__ void cp16(uint32_t dst, const void* src) {
    asm volatile("cp.async.cg.shared.global [%0], [%1], 16;"
                 :: "r"(dst), "l"(src) : "memory");
}
__device__ __forceinline__ void cp_commit() {
    asm volatile("cp.async.commit_group;" ::: "memory");
}
template <int N>
__device__ __forceinline__ void cp_wait() {
    asm volatile("cp.async.wait_group %0;" :: "n"(N) : "memory");
}

__device__ __forceinline__ void ldsm4(uint32_t r[4], uint32_t addr) {
    asm volatile("ldmatrix.sync.aligned.m8n8.x4.shared.b16 {%0,%1,%2,%3}, [%4];"
                 : "=r"(r[0]), "=r"(r[1]), "=r"(r[2]), "=r"(r[3]) : "r"(addr));
}

__device__ __forceinline__ void ldsm4t(uint32_t r[4], uint32_t addr) {
    asm volatile("ldmatrix.sync.aligned.m8n8.x4.trans.shared.b16 {%0,%1,%2,%3}, [%4];"
                 : "=r"(r[0]), "=r"(r[1]), "=r"(r[2]), "=r"(r[3]) : "r"(addr));
}

__device__ __forceinline__ void mma_f16(float c[4],
                                        const uint32_t a[4],
                                        uint32_t b0, uint32_t b1) {
    asm volatile(
        "mma.sync.aligned.m16n8k16.row.col.f32.f16.f16.f32 "
        "{%0,%1,%2,%3}, {%4,%5,%6,%7}, {%8,%9}, {%0,%1,%2,%3};"
        : "+f"(c[0]), "+f"(c[1]), "+f"(c[2]), "+f"(c[3])
        : "r"(a[0]), "r"(a[1]), "r"(a[2]), "r"(a[3]), "r"(b0), "r"(b1));
}

// Pack two fp32 into fp16x2 hi plane + fp16x2 residual lo plane.
__device__ __forceinline__ void cvt_hilo(float e0, float e1,
                                         uint32_t& hi, uint32_t& lo) {
    __half h0 = __float2half_rn(e0);
    __half h1 = __float2half_rn(e1);
    float r0 = e0 - __half2float(h0);
    float r1 = e1 - __half2float(h1);
    __half g0 = __float2half_rn(r0);
    __half g1 = __float2half_rn(r1);
    hi = ((uint32_t)__half_as_ushort(h1) << 16) | (uint32_t)__half_as_ushort(h0);
    lo = ((uint32_t)__half_as_ushort(g1) << 16) | (uint32_t)__half_as_ushort(g0);
}

__device__ __forceinline__ uint32_t cvt_hi2(float e0, float e1) {
    __half h0 = __float2half_rn(e0);
    __half h1 = __float2half_rn(e1);
    return ((uint32_t)__half_as_ushort(h1) << 16) | (uint32_t)__half_as_ushort(h0);
}

// ---------------------------------------------------------------------------
// Mask normalization (uint8 vs 4-byte storage detection)
// ---------------------------------------------------------------------------
__global__ void mask_convert_kernel(const unsigned char* __restrict__ raw, int n) {
    int i = blockIdx.x * blockDim.x + threadIdx.x;
    if (i >= n) return;
    bool one_byte = (raw[1] != 0);
    int v = one_byte ? (raw[i] != 0) : (((const unsigned int*)raw)[i] != 0u);
    g_valid[i] = v;
}

// ---------------------------------------------------------------------------
// Merged fp32 -> fp16 split: x (hi+lo), Wqkv (hi+lo), Wproj (hi only)
// Region-decoded over one grid.
// ---------------------------------------------------------------------------
#define NX_Q (MM * CC / 4)             // 1048576 quads
#define NWQ_Q (3 * CC * CC / 4)        // 786432
#define NWP_Q (CC * CC / 4)            // 262144

__global__ void split_all_kernel(const float* __restrict__ x,
                                 const float* __restrict__ Wqkv,
                                 const float* __restrict__ Wproj) {
    int i = blockIdx.x * blockDim.x + threadIdx.x;
    const float* in;
    __half *hi, *lo = nullptr;
    int idx;
    if (i < NX_Q) {
        in = x; hi = g_xhi; lo = g_xlo; idx = i;
    } else if (i < NX_Q + NWQ_Q) {
        in = Wqkv; hi = g_wqh; lo = g_wql; idx = i - NX_Q;
    } else if (i < NX_Q + NWQ_Q + NWP_Q) {
        in = Wproj; hi = g_wph; idx = i - NX_Q - NWQ_Q;
    } else {
        return;
    }
    float4 v = ((const float4*)in)[idx];
    if (lo) {
        uint32_t h0, l0, h1, l1;
        cvt_hilo(v.x, v.y, h0, l0);
        cvt_hilo(v.z, v.w, h1, l1);
        ((uint2*)hi)[idx] = make_uint2(h0, h1);
        ((uint2*)lo)[idx] = make_uint2(l0, l1);
    } else {
        ((uint2*)hi)[idx] = make_uint2(cvt_hi2(v.x, v.y), cvt_hi2(v.z, v.w));
    }
}

// ---------------------------------------------------------------------------
// HMMA GEMM (NT): C[M][N] = A[M][K] * W[N][K]^T + bias.
// CTA tile 128x256, 8 warps (2M x 4N), warp tile 64x64, mma m16n8k16,
// K-chunk 64 (128B rows, SW128), cp.async double buffer.
// PASSES=3: Ah*Wh + Ah*Wl + Al*Wh   (Wl pass skipped when n0 >= wl_limit)
// PASSES=2: (Ah+Al)*Wh              (Wlo never touched)
// SPLIT_OUT=1: write fp16 hi/lo planes; 0: write fp32.
// REMAP=1: 1D grid, heavy (n<8) tiles first, light V tiles in the tail wave.
// ---------------------------------------------------------------------------
template<int ROWS>
__device__ __forceinline__ void stage_cp(const __half* __restrict__ g,
                                         uint32_t sm_dst, int row0,
                                         int k_byte0, int tid) {
#pragma unroll
    for (int u = 0; u < ROWS / 32; ++u) {
        int s = u * 256 + tid;
        int row = s >> 3, seg = s & 7;
        const char* src = (const char*)g +
            (size_t)(row0 + row) * (CC * 2) + k_byte0 + seg * 16;
        uint32_t off = (uint32_t)(row * 128 + seg * 16);
        uint32_t sw = off ^ ((off >> 3) & 0x70);
        cp16(sm_dst + sw, src);
    }
}

template<int PASSES, int SPLIT_OUT, int REMAP>
__global__ __launch_bounds__(256) void gemm_mma_kernel(
    const __half* __restrict__ Ahi, const __half* __restrict__ Alo,
    const __half* __restrict__ Whi, const __half* __restrict__ Wlo,
    const float* __restrict__ bias,
    float* __restrict__ out, __half* __restrict__ outh, __half* __restrict__ outl,
    int N, int wl_limit)
{
    constexpr uint32_t STAGE = (PASSES == 3) ? 98304u : 65536u;
    extern __shared__ char dynsmem[];
    const int tid  = threadIdx.x;
    const int wid  = tid >> 5;
    const int lane = tid & 31;
    int m0, n0;
    if (REMAP) {
        int bid = blockIdx.x;
        int nt, mt;
        if (bid < 256) { nt = bid & 7;  mt = bid >> 3; }       // heavy Q,K tiles
        else { int b2 = bid - 256; nt = 8 + (b2 & 3); mt = b2 >> 2; }  // V tiles
        m0 = mt * 128;  n0 = nt * 256;
    } else {
        m0 = blockIdx.y * 128;
        n0 = blockIdx.x * 256;
    }
    const int wm = (wid >> 2) * 64;
    const int wn = (wid & 3) * 64;
    const bool use_wl = (PASSES == 3) && (n0 < wl_limit);

    uint32_t base = smem_u32(dynsmem);
    base = (base + 1023u) & ~1023u;

    float acc[4][8][4];
#pragma unroll
    for (int mt = 0; mt < 4; ++mt)
#pragma unroll
        for (int nt = 0; nt < 8; ++nt)
#pragma unroll
            for (int r = 0; r < 4; ++r) acc[mt][nt][r] = 0.f;

    const int sub = lane >> 3;
    const int lr  = lane & 7;
    int arow[4];  uint32_t axor[4];
#pragma unroll
    for (int mt = 0; mt < 4; ++mt) {
        arow[mt] = wm + mt * 16 + (sub & 1) * 8 + lr;
        axor[mt] = (uint32_t)((arow[mt] & 7) << 4);
    }
    const uint32_t acolH = (uint32_t)((sub >> 1) * 16);
    int brow[4];  uint32_t bxor[4];
#pragma unroll
    for (int np = 0; np < 4; ++np) {
        brow[np] = wn + np * 16 + (sub >> 1) * 8 + lr;
        bxor[np] = (uint32_t)((brow[np] & 7) << 4);
    }
    const uint32_t bcolH = (uint32_t)((sub & 1) * 16);

    const int NC = CC / 64;

    auto stage_all = [&](uint32_t sb, int kb) {
        stage_cp<128>(Ahi, sb,          m0, kb, tid);
        stage_cp<128>(Alo, sb + 16384,  m0, kb, tid);
        stage_cp<256>(Whi, sb + 32768,  n0, kb, tid);
        if (use_wl) stage_cp<256>(Wlo, sb + 65536, n0, kb, tid);
    };

    stage_all(base, 0);
    cp_commit();

    for (int c = 0; c < NC; ++c) {
        if (c + 1 < NC) {
            stage_all(base + (uint32_t)((c + 1) & 1) * STAGE, (c + 1) * 128);
            cp_commit();
            cp_wait<1>();
        } else {
            cp_wait<0>();
        }
        __syncthreads();

        uint32_t sb  = base + (uint32_t)(c & 1) * STAGE;
        uint32_t aH = sb, aL = sb + 16384, bH = sb + 32768, bL = sb + 65536;

#pragma unroll
        for (int ks = 0; ks < 4; ++ks) {
            uint32_t kA = (uint32_t)(ks * 32) + acolH;
            uint32_t kB = (uint32_t)(ks * 32) + bcolH;
            uint32_t ah[4][4], al[4][4];
#pragma unroll
            for (int mt = 0; mt < 4; ++mt) {
                uint32_t rofs = (uint32_t)(arow[mt] * 128) + (kA ^ axor[mt]);
                ldsm4(ah[mt], aH + rofs);
                ldsm4(al[mt], aL + rofs);
            }
#pragma unroll
            for (int np = 0; np < 4; ++np) {
                uint32_t rofs = (uint32_t)(brow[np] * 128) + (kB ^ bxor[np]);
                uint32_t bh[4], bl[4];
                ldsm4(bh, bH + rofs);
                if (use_wl) ldsm4(bl, bL + rofs);
#pragma unroll
                for (int mt = 0; mt < 4; ++mt) {
#pragma unroll
                    for (int half = 0; half < 2; ++half) {
                        int nt = np * 2 + half;
                        int o = half * 2;
                        mma_f16(acc[mt][nt], ah[mt], bh[o], bh[o + 1]);
                        if (use_wl)
                            mma_f16(acc[mt][nt], ah[mt], bl[o], bl[o + 1]);
                        mma_f16(acc[mt][nt], al[mt], bh[o], bh[o + 1]);
                    }
                }
            }
        }
        __syncthreads();
    }

    const int erow = m0 + wm + (lane >> 2);
    const int ecol0 = n0 + wn + (lane & 3) * 2;
#pragma unroll
    for (int mt = 0; mt < 4; ++mt) {
#pragma unroll
        for (int nt = 0; nt < 8; ++nt) {
            int row = erow + mt * 16;
            int col = ecol0 + nt * 8;
            float b0 = bias[col], b1 = bias[col + 1];
            float a0 = acc[mt][nt][0] + b0, a1 = acc[mt][nt][1] + b1;
            float a2 = acc[mt][nt][2] + b0, a3 = acc[mt][nt][3] + b1;
            if (SPLIT_OUT) {
                uint32_t hi0, lo0, hi1, lo1;
                cvt_hilo(a0, a1, hi0, lo0);
                cvt_hilo(a2, a3, hi1, lo1);
                *(uint32_t*)(outh + (size_t)row * N + col) = hi0;
                *(uint32_t*)(outl + (size_t)row * N + col) = lo0;
                *(uint32_t*)(outh + (size_t)(row + 8) * N + col) = hi1;
                *(uint32_t*)(outl + (size_t)(row + 8) * N + col) = lo1;
            } else {
                *(float2*)(out + (size_t)row * N + col) = make_float2(a0, a1);
                *(float2*)(out + (size_t)(row + 8) * N + col) = make_float2(a2, a3);
            }
        }
    }
}

// ---------------------------------------------------------------------------
// HMMA flash attention (fp16 planes, cp.async, double-buffered KV).
// Now __launch_bounds__(256, 2): 2 CTAs/SM (smem 81KB x 2 fits 227KB).
// ---------------------------------------------------------------------------
#define AT_QH 0
#define AT_QL 16384
#define AT_KV 32768
#define AT_BUF 24576
#define ATTN_DYN (32768 + 2 * 24576 + 1024)

__global__ __launch_bounds__(256, 2) void attn_mma_kernel() {
    extern __shared__ char asmem[];
    __shared__ int vflag[64];

    uint32_t sb = smem_u32(asmem);
    sb = (sb + 1023u) & ~1023u;

    const int tid  = threadIdx.x;
    const int wid  = tid >> 5;
    const int lane = tid & 31;
    const int qb = 15 - blockIdx.x;       // heavy tiles first
    const int h  = blockIdx.y;
    const int b  = blockIdx.z;
    const int wq = wid * 16;
    const int niter = 2 * qb + 2;

    {
        const char* qh = (const char*)(g_qkvh + (size_t)(b * TT + qb * 128) * 3072 + h * 64);
        const char* ql = (const char*)(g_qkvl + (size_t)(b * TT + qb * 128) * 3072 + h * 64);
#pragma unroll
        for (int u = 0; u < 4; ++u) {
            int s = u * 256 + tid;
            int row = s >> 3, seg = s & 7;
            uint32_t off = (uint32_t)(row * 128 + ((seg * 16) ^ ((row & 7) << 4)));
            cp16(sb + AT_QH + off, qh + (size_t)row * 6144 + seg * 16);
            cp16(sb + AT_QL + off, ql + (size_t)row * 6144 + seg * 16);
        }
    }
    auto stage_kv = [&](int kbn, uint32_t bufb) {
        size_t rb = (size_t)(b * TT + kbn * 64) * 3072 + h * 64;
        const char* kh = (const char*)(g_qkvh + rb + 1024);
        const char* kl = (const char*)(g_qkvl + rb + 1024);
        const char* vh = (const char*)(g_qkvh + rb + 2048);
#pragma unroll
        for (int u = 0; u < 2; ++u) {
            int s = u * 256 + tid;
            int row = s >> 3, seg = s & 7;
            uint32_t off = (uint32_t)(row * 128 + ((seg * 16) ^ ((row & 7) << 4)));
            cp16(bufb + off,         kh + (size_t)row * 6144 + seg * 16);
            cp16(bufb + 8192 + off,  kl + (size_t)row * 6144 + seg * 16);
            cp16(bufb + 16384 + off, vh + (size_t)row * 6144 + seg * 16);
        }
    };
    stage_kv(0, sb + AT_KV);
    cp_commit();

    const int sub = lane >> 3;
    const int lr  = lane & 7;
    const uint32_t a_row  = (uint32_t)(wq + ((sub & 1) << 3) + lr);
    const uint32_t a_colH = (uint32_t)((sub >> 1) << 4);
    const uint32_t a_xor  = (uint32_t)(lr << 4);
    const uint32_t b_rowH = (uint32_t)(((sub >> 1) << 3) + lr);
    const uint32_t b_colH = (uint32_t)((sub & 1) << 4);
    const int vt = lane >> 3, vlr = lane & 7;
    const uint32_t v_rowH = (uint32_t)(((vt & 1) << 3) + vlr);
    const uint32_t v_colH = (uint32_t)((vt >> 1) << 4);
    const uint32_t v_xor  = (uint32_t)(vlr << 4);

    const int r   = lane >> 2;
    const int c0l = (lane & 3) * 2;
    const int qg0 = qb * 128 + wq + r;
    const int qg1 = qg0 + 8;
    const float scale = 0.125f;

    float oacc[8][4];
#pragma unroll
    for (int j = 0; j < 8; ++j)
#pragma unroll
        for (int e = 0; e < 4; ++e) oacc[j][e] = 0.f;
    float m0 = -1e30f, m1 = -1e30f, l0 = 0.f, l1 = 0.f;

    for (int kb = 0; kb < niter; ++kb) {
        int my = (tid < 64) ? g_valid[b * TT + kb * 64 + tid] : 0;
        int any = __syncthreads_or(my);
        if (tid < 64) vflag[tid] = my;

        if (kb + 1 < niter) {
            stage_kv(kb + 1, sb + AT_KV + (uint32_t)((kb + 1) & 1) * AT_BUF);
            cp_commit();
            cp_wait<1>();
        } else {
            cp_wait<0>();
        }
        __syncthreads();
        if (!any) continue;

        uint32_t kvb = sb + AT_KV + (uint32_t)(kb & 1) * AT_BUF;
        uint32_t kH = kvb, kL = kvb + 8192, vH = kvb + 16384;

        float sacc[8][4];
#pragma unroll
        for (int j = 0; j < 8; ++j)
#pragma unroll
            for (int e = 0; e < 4; ++e) sacc[j][e] = 0.f;

#pragma unroll
        for (int kt = 0; kt < 4; ++kt) {
            uint32_t aofs = a_row * 128 + (((uint32_t)(kt * 32) + a_colH) ^ a_xor);
            uint32_t ah[4], al[4];
            ldsm4(ah, sb + AT_QH + aofs);
            ldsm4(al, sb + AT_QL + aofs);
#pragma unroll
            for (int np = 0; np < 4; ++np) {
                uint32_t brow = (uint32_t)(np * 16) + b_rowH;
                uint32_t bofs = brow * 128 +
                    (((uint32_t)(kt * 32) + b_colH) ^ ((brow & 7) << 4));
                uint32_t bh[4], bl[4];
                ldsm4(bh, kH + bofs);
                ldsm4(bl, kL + bofs);
                mma_f16(sacc[2 * np],     ah, bh[0], bh[1]);
                mma_f16(sacc[2 * np],     ah, bl[0], bl[1]);
                mma_f16(sacc[2 * np],     al, bh[0], bh[1]);
                mma_f16(sacc[2 * np + 1], ah, bh[2], bh[3]);
                mma_f16(sacc[2 * np + 1], ah, bl[2], bl[3]);
                mma_f16(sacc[2 * np + 1], al, bh[2], bh[3]);
            }
        }

        float mx0 = -1e30f, mx1 = -1e30f;
#pragma unroll
        for (int j = 0; j < 8; ++j) {
            int col0 = 8 * j + c0l;
            int k0 = kb * 64 + col0, k1 = k0 + 1;
            int v0 = vflag[col0], v1 = vflag[col0 + 1];
            float s0 = (v0 && k0 <= qg0) ? sacc[j][0] * scale : -1e30f;
            float s1 = (v1 && k1 <= qg0) ? sacc[j][1] * scale : -1e30f;
            float s2 = (v0 && k0 <= qg1) ? sacc[j][2] * scale : -1e30f;
            float s3 = (v1 && k1 <= qg1) ? sacc[j][3] * scale : -1e30f;
            sacc[j][0] = s0; sacc[j][1] = s1; sacc[j][2] = s2; sacc[j][3] = s3;
            mx0 = fmaxf(mx0, fmaxf(s0, s1));
            mx1 = fmaxf(mx1, fmaxf(s2, s3));
        }
        mx0 = fmaxf(mx0, __shfl_xor_sync(0xffffffffu, mx0, 1));
        mx0 = fmaxf(mx0, __shfl_xor_sync(0xffffffffu, mx0, 2));
        mx1 = fmaxf(mx1, __shfl_xor_sync(0xffffffffu, mx1, 1));
        mx1 = fmaxf(mx1, __shfl_xor_sync(0xffffffffu, mx1, 2));

        float mn0 = fmaxf(m0, mx0), mn1 = fmaxf(m1, mx1);
        float al0 = __expf(m0 - mn0), al1 = __expf(m1 - mn1);
        m0 = mn0; m1 = mn1;

        float rs0 = 0.f, rs1 = 0.f;
#pragma unroll
        for (int j = 0; j < 8; ++j) {
            sacc[j][0] = __expf(sacc[j][0] - mn0);
            sacc[j][1] = __expf(sacc[j][1] - mn0);
            sacc[j][2] = __expf(sacc[j][2] - mn1);
            sacc[j][3] = __expf(sacc[j][3] - mn1);
            rs0 += sacc[j][0] + sacc[j][1];
            rs1 += sacc[j][2] + sacc[j][3];
        }
        rs0 += __shfl_xor_sync(0xffffffffu, rs0, 1);
        rs0 += __shfl_xor_sync(0xffffffffu, rs0, 2);
        rs1 += __shfl_xor_sync(0xffffffffu, rs1, 1);
        rs1 += __shfl_xor_sync(0xffffffffu, rs1, 2);
        l0 = l0 * al0 + rs0;
        l1 = l1 * al1 + rs1;
#pragma unroll
        for (int j = 0; j < 8; ++j) {
            oacc[j][0] *= al0; oacc[j][1] *= al0;
            oacc[j][2] *= al1; oacc[j][3] *= al1;
        }

#pragma unroll
        for (int kt = 0; kt < 4; ++kt) {
            uint32_t ph[4], pl[4];
            cvt_hilo(sacc[2 * kt][0],     sacc[2 * kt][1],     ph[0], pl[0]);
            cvt_hilo(sacc[2 * kt][2],     sacc[2 * kt][3],     ph[1], pl[1]);
            cvt_hilo(sacc[2 * kt + 1][0], sacc[2 * kt + 1][1], ph[2], pl[2]);
            cvt_hilo(sacc[2 * kt + 1][2], sacc[2 * kt + 1][3], ph[3], pl[3]);
#pragma unroll
            for (int j2 = 0; j2 < 4; ++j2) {
                uint32_t vrow = (uint32_t)(kt * 16) + v_rowH;
                uint32_t vofs = vrow * 128 +
                    (((uint32_t)(j2 * 32) + v_colH) ^ v_xor);
                uint32_t vh[4];
                ldsm4t(vh, vH + vofs);
                mma_f16(oacc[2 * j2],     ph, vh[0], vh[1]);
                mma_f16(oacc[2 * j2],     pl, vh[0], vh[1]);
                mma_f16(oacc[2 * j2 + 1], ph, vh[2], vh[3]);
                mma_f16(oacc[2 * j2 + 1], pl, vh[2], vh[3]);
            }
        }
    }

    float inv0 = 1.f / l0, inv1 = 1.f / l1;
    const size_t row0 = (size_t)b * TT + qb * 128 + wq + r;
#pragma unroll
    for (int j = 0; j < 8; ++j) {
        int col = h * DD + 8 * j + c0l;
        uint32_t hi0, lo0, hi1, lo1;
        cvt_hilo(oacc[j][0] * inv0, oacc[j][1] * inv0, hi0, lo0);
        cvt_hilo(oacc[j][2] * inv1, oacc[j][3] * inv1, hi1, lo1);
        *(uint32_t*)(g_ah + row0 * CC + col) = hi0;
        *(uint32_t*)(g_al + row0 * CC + col) = lo0;
        *(uint32_t*)(g_ah + (row0 + 8) * CC + col) = hi1;
        *(uint32_t*)(g_al + (row0 + 8) * CC + col) = lo1;
    }
}

// ---------------------------------------------------------------------------
// Launch
// ---------------------------------------------------------------------------
extern "C" void kernel_launch(void* const* d_in, const int* in_sizes, int n_in,
                              void* d_out, int out_size) {
    const float*         x     = (const float*)d_in[0];
    const unsigned char* mask  = (const unsigned char*)d_in[1];
    const float*         Wqkv  = (const float*)d_in[2];
    const float*         bqkv  = (const float*)d_in[3];
    const float*         Wproj = (const float*)d_in[4];
    const float*         bproj = (const float*)d_in[5];
    float*               out   = (float*)d_out;

    __half *xhi, *xlo, *wqh, *wql, *wph, *qkvh, *qkvl, *ahi, *alo;
    cudaGetSymbolAddress((void**)&xhi,  g_xhi);
    cudaGetSymbolAddress((void**)&xlo,  g_xlo);
    cudaGetSymbolAddress((void**)&wqh,  g_wqh);
    cudaGetSymbolAddress((void**)&wql,  g_wql);
    cudaGetSymbolAddress((void**)&wph,  g_wph);
    cudaGetSymbolAddress((void**)&qkvh, g_qkvh);
    cudaGetSymbolAddress((void**)&qkvl, g_qkvl);
    cudaGetSymbolAddress((void**)&ahi,  g_ah);
    cudaGetSymbolAddress((void**)&alo,  g_al);

    // 1. mask
    {
        int n = BB * TT;
        mask_convert_kernel<<<(n + 255) / 256, 256>>>(mask, n);
    }

    // 2. merged splits
    {
        int total = NX_Q + NWQ_Q + NWP_Q;
        split_all_kernel<<<(total + 255) / 256, 256>>>(x, Wqkv, Wproj);
    }

    // 3. QKV projection: 3-pass (Q,K) / 2-pass (V), heavy-first 1D grid
    {
        const int dyn = 2 * 98304 + 1024;
        cudaFuncSetAttribute(gemm_mma_kernel<3, 1, 1>,
                             cudaFuncAttributeMaxDynamicSharedMemorySize, dyn);
        gemm_mma_kernel<3, 1, 1><<<384, 256, dyn>>>(
            xhi, xlo, wqh, wql, bqkv, nullptr, qkvh, qkvl, 3 * CC, 2 * CC);
    }

    // 4. Attention (fp16 planes in/out, 2 CTAs/SM)
    {
        cudaFuncSetAttribute(attn_mma_kernel,
                             cudaFuncAttributeMaxDynamicSharedMemorySize,
                             ATTN_DYN);
        dim3 grid(TT / 128, HH, BB);
        attn_mma_kernel<<<grid, 256, ATTN_DYN>>>();
    }

    // 5. Output projection: 2-pass, fp32 output (single wave: 128 CTAs)
    {
        const int dyn = 2 * 65536 + 1024;
        cudaFuncSetAttribute(gemm_mma_kernel<2, 0, 0>,
                             cudaFuncAttributeMaxDynamicSharedMemorySize, dyn);
        dim3 grid(CC / 256, MM / 128);
        gemm_mma_kernel<2, 0, 0><<<grid, 256, dyn>>>(
            ahi, alo, wph, wph, bproj, out, nullptr, nullptr, CC, 0);
    }
}

// round 12
// speedup vs baseline: 3.9429x; 1.1354x over previous
#include <cuda_runtime.h>
#include <cuda_fp16.h>
#include <cstdint>

// Problem constants
#define BB 2
#define TT 2048
#define CC 1024
#define HH 16
#define DD 64
#define MM (BB * TT)          // 4096 rows

// ---------------------------------------------------------------------------
// Scratch (__device__ globals; allocation-free rule)
// ---------------------------------------------------------------------------
__device__ int    g_len[BB];
__device__ __half g_xhi[(size_t)MM * CC];
__device__ __half g_xlo[(size_t)MM * CC];
__device__ __half g_wqh[(size_t)3 * CC * CC];
__device__ __half g_wql[(size_t)3 * CC * CC];
__device__ __half g_wph[(size_t)CC * CC];
__device__ __half g_qkvh[(size_t)MM * 3 * CC];   // (B,T,3C) fp16 hi plane
__device__ __half g_qkvl[(size_t)MM * 3 * CC];   // lo plane
__device__ __half g_ah[(size_t)MM * CC];         // attention out hi
__device__ __half g_al[(size_t)MM * CC];         // attention out lo

// ---------------------------------------------------------------------------
// PTX helpers (baseline features only: valid for compute_103)
// ---------------------------------------------------------------------------
__device__ __forceinline__ uint32_t smem_u32(const void* p) {
    uint32_t a;
    asm("{ .reg .u64 t; cvta.to.shared.u64 t, %1; cvt.u32.u64 %0, t; }"
        : "=r"(a) : "l"(p));
    return a;
}

__device__ __forceinline__ void cp16(uint32_t dst, const void* src) {
    asm volatile("cp.async.cg.shared.global [%0], [%1], 16;"
                 :: "r"(dst), "l"(src) : "memory");
}
__device__ __forceinline__ void cp_commit() {
    asm volatile("cp.async.commit_group;" ::: "memory");
}
template <int N>
__device__ __forceinline__ void cp_wait() {
    asm volatile("cp.async.wait_group %0;" :: "n"(N) : "memory");
}

__device__ __forceinline__ void ldsm4(uint32_t r[4], uint32_t addr) {
    asm volatile("ldmatrix.sync.aligned.m8n8.x4.shared.b16 {%0,%1,%2,%3}, [%4];"
                 : "=r"(r[0]), "=r"(r[1]), "=r"(r[2]), "=r"(r[3]) : "r"(addr));
}

__device__ __forceinline__ void ldsm4t(uint32_t r[4], uint32_t addr) {
    asm volatile("ldmatrix.sync.aligned.m8n8.x4.trans.shared.b16 {%0,%1,%2,%3}, [%4];"
                 : "=r"(r[0]), "=r"(r[1]), "=r"(r[2]), "=r"(r[3]) : "r"(addr));
}

__device__ __forceinline__ void mma_f16(float c[4],
                                        const uint32_t a[4],
                                        uint32_t b0, uint32_t b1) {
    asm volatile(
        "mma.sync.aligned.m16n8k16.row.col.f32.f16.f16.f32 "
        "{%0,%1,%2,%3}, {%4,%5,%6,%7}, {%8,%9}, {%0,%1,%2,%3};"
        : "+f"(c[0]), "+f"(c[1]), "+f"(c[2]), "+f"(c[3])
        : "r"(a[0]), "r"(a[1]), "r"(a[2]), "r"(a[3]), "r"(b0), "r"(b1));
}

__device__ __forceinline__ float ex2(float x) {
    float r;
    asm("ex2.approx.f32 %0, %1;" : "=f"(r) : "f"(x));
    return r;
}

// Pack two fp32 into fp16x2 hi plane + fp16x2 residual lo plane.
__device__ __forceinline__ void cvt_hilo(float e0, float e1,
                                         uint32_t& hi, uint32_t& lo) {
    __half h0 = __float2half_rn(e0);
    __half h1 = __float2half_rn(e1);
    float r0 = e0 - __half2float(h0);
    float r1 = e1 - __half2float(h1);
    __half g0 = __float2half_rn(r0);
    __half g1 = __float2half_rn(r1);
    hi = ((uint32_t)__half_as_ushort(h1) << 16) | (uint32_t)__half_as_ushort(h0);
    lo = ((uint32_t)__half_as_ushort(g1) << 16) | (uint32_t)__half_as_ushort(g0);
}

__device__ __forceinline__ uint32_t cvt_hi2(float e0, float e1) {
    __half h0 = __float2half_rn(e0);
    __half h1 = __float2half_rn(e1);
    return ((uint32_t)__half_as_ushort(h1) << 16) | (uint32_t)__half_as_ushort(h0);
}

// ---------------------------------------------------------------------------
// Per-batch valid length (mask is a prefix by construction: arange < length).
// Handles uint8 or 4-byte mask storage. One block per batch.
// ---------------------------------------------------------------------------
__global__ void len_kernel(const unsigned char* __restrict__ raw) {
    __shared__ int red[256];
    int b = blockIdx.x;
    int tid = threadIdx.x;
    bool one_byte = (raw[1] != 0);
    int cnt = 0;
    for (int i = tid; i < TT; i += 256) {
        int v = one_byte ? (raw[b * TT + i] != 0)
                         : (((const unsigned int*)raw)[b * TT + i] != 0u);
        cnt += v;
    }
    red[tid] = cnt;
    __syncthreads();
    for (int s = 128; s > 0; s >>= 1) {
        if (tid < s) red[tid] += red[tid + s];
        __syncthreads();
    }
    if (tid == 0) g_len[b] = red[0];
}

// ---------------------------------------------------------------------------
// Merged fp32 -> fp16 split: x (hi+lo), Wqkv (hi+lo), Wproj (hi only)
// ---------------------------------------------------------------------------
#define NX_Q (MM * CC / 4)             // 1048576 quads
#define NWQ_Q (3 * CC * CC / 4)        // 786432
#define NWP_Q (CC * CC / 4)            // 262144

__global__ void split_all_kernel(const float* __restrict__ x,
                                 const float* __restrict__ Wqkv,
                                 const float* __restrict__ Wproj) {
    int i = blockIdx.x * blockDim.x + threadIdx.x;
    const float* in;
    __half *hi, *lo = nullptr;
    int idx;
    if (i < NX_Q) {
        in = x; hi = g_xhi; lo = g_xlo; idx = i;
    } else if (i < NX_Q + NWQ_Q) {
        in = Wqkv; hi = g_wqh; lo = g_wql; idx = i - NX_Q;
    } else if (i < NX_Q + NWQ_Q + NWP_Q) {
        in = Wproj; hi = g_wph; idx = i - NX_Q - NWQ_Q;
    } else {
        return;
    }
    float4 v = ((const float4*)in)[idx];
    if (lo) {
        uint32_t h0, l0, h1, l1;
        cvt_hilo(v.x, v.y, h0, l0);
        cvt_hilo(v.z, v.w, h1, l1);
        ((uint2*)hi)[idx] = make_uint2(h0, h1);
        ((uint2*)lo)[idx] = make_uint2(l0, l1);
    } else {
        ((uint2*)hi)[idx] = make_uint2(cvt_hi2(v.x, v.y), cvt_hi2(v.z, v.w));
    }
}

// ---------------------------------------------------------------------------
// HMMA GEMM (NT): unchanged from Round 6 (validated).
// ---------------------------------------------------------------------------
template<int ROWS>
__device__ __forceinline__ void stage_cp(const __half* __restrict__ g,
                                         uint32_t sm_dst, int row0,
                                         int k_byte0, int tid) {
#pragma unroll
    for (int u = 0; u < ROWS / 32; ++u) {
        int s = u * 256 + tid;
        int row = s >> 3, seg = s & 7;
        const char* src = (const char*)g +
            (size_t)(row0 + row) * (CC * 2) + k_byte0 + seg * 16;
        uint32_t off = (uint32_t)(row * 128 + seg * 16);
        uint32_t sw = off ^ ((off >> 3) & 0x70);
        cp16(sm_dst + sw, src);
    }
}

template<int PASSES, int SPLIT_OUT, int REMAP>
__global__ __launch_bounds__(256) void gemm_mma_kernel(
    const __half* __restrict__ Ahi, const __half* __restrict__ Alo,
    const __half* __restrict__ Whi, const __half* __restrict__ Wlo,
    const float* __restrict__ bias,
    float* __restrict__ out, __half* __restrict__ outh, __half* __restrict__ outl,
    int N, int wl_limit)
{
    constexpr uint32_t STAGE = (PASSES == 3) ? 98304u : 65536u;
    extern __shared__ char dynsmem[];
    const int tid  = threadIdx.x;
    const int wid  = tid >> 5;
    const int lane = tid & 31;
    int m0, n0;
    if (REMAP) {
        int bid = blockIdx.x;
        int nt, mt;
        if (bid < 256) { nt = bid & 7;  mt = bid >> 3; }
        else { int b2 = bid - 256; nt = 8 + (b2 & 3); mt = b2 >> 2; }
        m0 = mt * 128;  n0 = nt * 256;
    } else {
        m0 = blockIdx.y * 128;
        n0 = blockIdx.x * 256;
    }
    const int wm = (wid >> 2) * 64;
    const int wn = (wid & 3) * 64;
    const bool use_wl = (PASSES == 3) && (n0 < wl_limit);

    uint32_t base = smem_u32(dynsmem);
    base = (base + 1023u) & ~1023u;

    float acc[4][8][4];
#pragma unroll
    for (int mt = 0; mt < 4; ++mt)
#pragma unroll
        for (int nt = 0; nt < 8; ++nt)
#pragma unroll
            for (int r = 0; r < 4; ++r) acc[mt][nt][r] = 0.f;

    const int sub = lane >> 3;
    const int lr  = lane & 7;
    int arow[4];  uint32_t axor[4];
#pragma unroll
    for (int mt = 0; mt < 4; ++mt) {
        arow[mt] = wm + mt * 16 + (sub & 1) * 8 + lr;
        axor[mt] = (uint32_t)((arow[mt] & 7) << 4);
    }
    const uint32_t acolH = (uint32_t)((sub >> 1) * 16);
    int brow[4];  uint32_t bxor[4];
#pragma unroll
    for (int np = 0; np < 4; ++np) {
        brow[np] = wn + np * 16 + (sub >> 1) * 8 + lr;
        bxor[np] = (uint32_t)((brow[np] & 7) << 4);
    }
    const uint32_t bcolH = (uint32_t)((sub & 1) * 16);

    const int NC = CC / 64;

    auto stage_all = [&](uint32_t sb, int kb) {
        stage_cp<128>(Ahi, sb,          m0, kb, tid);
        stage_cp<128>(Alo, sb + 16384,  m0, kb, tid);
        stage_cp<256>(Whi, sb + 32768,  n0, kb, tid);
        if (use_wl) stage_cp<256>(Wlo, sb + 65536, n0, kb, tid);
    };

    stage_all(base, 0);
    cp_commit();

    for (int c = 0; c < NC; ++c) {
        if (c + 1 < NC) {
            stage_all(base + (uint32_t)((c + 1) & 1) * STAGE, (c + 1) * 128);
            cp_commit();
            cp_wait<1>();
        } else {
            cp_wait<0>();
        }
        __syncthreads();

        uint32_t sb  = base + (uint32_t)(c & 1) * STAGE;
        uint32_t aH = sb, aL = sb + 16384, bH = sb + 32768, bL = sb + 65536;

#pragma unroll
        for (int ks = 0; ks < 4; ++ks) {
            uint32_t kA = (uint32_t)(ks * 32) + acolH;
            uint32_t kB = (uint32_t)(ks * 32) + bcolH;
            uint32_t ah[4][4], al[4][4];
#pragma unroll
            for (int mt = 0; mt < 4; ++mt) {
                uint32_t rofs = (uint32_t)(arow[mt] * 128) + (kA ^ axor[mt]);
                ldsm4(ah[mt], aH + rofs);
                ldsm4(al[mt], aL + rofs);
            }
#pragma unroll
            for (int np = 0; np < 4; ++np) {
                uint32_t rofs = (uint32_t)(brow[np] * 128) + (kB ^ bxor[np]);
                uint32_t bh[4], bl[4];
                ldsm4(bh, bH + rofs);
                if (use_wl) ldsm4(bl, bL + rofs);
#pragma unroll
                for (int mt = 0; mt < 4; ++mt) {
#pragma unroll
                    for (int half = 0; half < 2; ++half) {
                        int nt = np * 2 + half;
                        int o = half * 2;
                        mma_f16(acc[mt][nt], ah[mt], bh[o], bh[o + 1]);
                        if (use_wl)
                            mma_f16(acc[mt][nt], ah[mt], bl[o], bl[o + 1]);
                        mma_f16(acc[mt][nt], al[mt], bh[o], bh[o + 1]);
                    }
                }
            }
        }
        __syncthreads();
    }

    const int erow = m0 + wm + (lane >> 2);
    const int ecol0 = n0 + wn + (lane & 3) * 2;
#pragma unroll
    for (int mt = 0; mt < 4; ++mt) {
#pragma unroll
        for (int nt = 0; nt < 8; ++nt) {
            int row = erow + mt * 16;
            int col = ecol0 + nt * 8;
            float b0 = bias[col], b1 = bias[col + 1];
            float a0 = acc[mt][nt][0] + b0, a1 = acc[mt][nt][1] + b1;
            float a2 = acc[mt][nt][2] + b0, a3 = acc[mt][nt][3] + b1;
            if (SPLIT_OUT) {
                uint32_t hi0, lo0, hi1, lo1;
                cvt_hilo(a0, a1, hi0, lo0);
                cvt_hilo(a2, a3, hi1, lo1);
                *(uint32_t*)(outh + (size_t)row * N + col) = hi0;
                *(uint32_t*)(outl + (size_t)row * N + col) = lo0;
                *(uint32_t*)(outh + (size_t)(row + 8) * N + col) = hi1;
                *(uint32_t*)(outl + (size_t)(row + 8) * N + col) = lo1;
            } else {
                *(float2*)(out + (size_t)row * N + col) = make_float2(a0, a1);
                *(float2*)(out + (size_t)(row + 8) * N + col) = make_float2(a2, a3);
            }
        }
    }
}

// ---------------------------------------------------------------------------
// HMMA flash attention, v2:
//  - prefix mask: per-thread kmax compare, loop truncated to ceil(len/64)
//  - triple-buffered KV, ONE __syncthreads per iteration
//  - ex2-based softmax (log2e folded into scale)
//  - 1D grid sorted heavy-first (all qb=15 CTAs first)
// smem: Qh 16K + Ql 16K + 3 x 24K = 104K (+pad) -> 2 CTAs/SM.
// ---------------------------------------------------------------------------
#define AT_QH 0
#define AT_QL 16384
#define AT_KV 32768
#define AT_BUF 24576
#define ATTN_DYN (32768 + 3 * 24576 + 1024)

__global__ __launch_bounds__(256, 2) void attn_mma_kernel() {
    extern __shared__ char asmem[];

    uint32_t sb = smem_u32(asmem);
    sb = (sb + 1023u) & ~1023u;

    const int tid  = threadIdx.x;
    const int wid  = tid >> 5;
    const int lane = tid & 31;
    const int bid  = blockIdx.x;
    const int qb   = 15 - (bid >> 5);       // sorted: heaviest first
    const int h    = bid & 15;
    const int b    = (bid >> 4) & 1;
    const int wq   = wid * 16;
    const int len  = g_len[b];
    const int niter_c = 2 * qb + 2;
    const int niter_m = (len + 63) >> 6;
    const int niter = niter_c < niter_m ? niter_c : niter_m;

    // ---- Stage Q (both planes) + KV tiles 0,1 via cp.async ----
    {
        const char* qh = (const char*)(g_qkvh + (size_t)(b * TT + qb * 128) * 3072 + h * 64);
        const char* ql = (const char*)(g_qkvl + (size_t)(b * TT + qb * 128) * 3072 + h * 64);
#pragma unroll
        for (int u = 0; u < 4; ++u) {
            int s = u * 256 + tid;
            int row = s >> 3, seg = s & 7;
            uint32_t off = (uint32_t)(row * 128 + ((seg * 16) ^ ((row & 7) << 4)));
            cp16(sb + AT_QH + off, qh + (size_t)row * 6144 + seg * 16);
            cp16(sb + AT_QL + off, ql + (size_t)row * 6144 + seg * 16);
        }
    }
    auto stage_kv = [&](int kbn, uint32_t bufb) {
        size_t rb = (size_t)(b * TT + kbn * 64) * 3072 + h * 64;
        const char* kh = (const char*)(g_qkvh + rb + 1024);
        const char* kl = (const char*)(g_qkvl + rb + 1024);
        const char* vh = (const char*)(g_qkvh + rb + 2048);
#pragma unroll
        for (int u = 0; u < 2; ++u) {
            int s = u * 256 + tid;
            int row = s >> 3, seg = s & 7;
            uint32_t off = (uint32_t)(row * 128 + ((seg * 16) ^ ((row & 7) << 4)));
            cp16(bufb + off,         kh + (size_t)row * 6144 + seg * 16);
            cp16(bufb + 8192 + off,  kl + (size_t)row * 6144 + seg * 16);
            cp16(bufb + 16384 + off, vh + (size_t)row * 6144 + seg * 16);
        }
    };
    stage_kv(0, sb + AT_KV);          // group 0 (with Q)
    cp_commit();
    stage_kv(1, sb + AT_KV + AT_BUF); // group 1 (niter >= 2 always)
    cp_commit();

    const int sub = lane >> 3;
    const int lr  = lane & 7;
    const uint32_t a_row  = (uint32_t)(wq + ((sub & 1) << 3) + lr);
    const uint32_t a_colH = (uint32_t)((sub >> 1) << 4);
    const uint32_t a_xor  = (uint32_t)(lr << 4);
    const uint32_t b_rowH = (uint32_t)(((sub >> 1) << 3) + lr);
    const uint32_t b_colH = (uint32_t)((sub & 1) << 4);
    const int vt = lane >> 3, vlr = lane & 7;
    const uint32_t v_rowH = (uint32_t)(((vt & 1) << 3) + vlr);
    const uint32_t v_colH = (uint32_t)((vt >> 1) << 4);
    const uint32_t v_xor  = (uint32_t)(vlr << 4);

    const int r   = lane >> 2;
    const int c0l = (lane & 3) * 2;
    const int qg0 = qb * 128 + wq + r;
    const int qg1 = qg0 + 8;
    const int kmax0 = qg0 < (len - 1) ? qg0 : (len - 1);
    const int kmax1 = qg1 < (len - 1) ? qg1 : (len - 1);
    const float scale2 = 0.125f * 1.44269504089f;   // 1/sqrt(D) * log2(e)

    float oacc[8][4];
#pragma unroll
    for (int j = 0; j < 8; ++j)
#pragma unroll
        for (int e = 0; e < 4; ++e) oacc[j][e] = 0.f;
    float m0 = -1e30f, m1 = -1e30f, l0 = 0.f, l1 = 0.f;

    for (int kb = 0; kb < niter; ++kb) {
        // Pipeline: groups committed so far = min(kb+2, niter).
        // wait<1> guarantees group kb complete while kb+2 < niter;
        // wait<0> covers the tail (no further commits).
        if (kb + 2 < niter) cp_wait<1>(); else cp_wait<0>();
        __syncthreads();    // data visibility + buffer-reuse safety
        if (kb + 2 < niter) {
            stage_kv(kb + 2, sb + AT_KV + (uint32_t)((kb + 2) % 3) * AT_BUF);
            cp_commit();
        }

        uint32_t kvb = sb + AT_KV + (uint32_t)(kb % 3) * AT_BUF;
        uint32_t kH = kvb, kL = kvb + 8192, vH = kvb + 16384;

        // ---- S = Q K^T (3-pass) ----
        float sacc[8][4];
#pragma unroll
        for (int j = 0; j < 8; ++j)
#pragma unroll
            for (int e = 0; e < 4; ++e) sacc[j][e] = 0.f;

#pragma unroll
        for (int kt = 0; kt < 4; ++kt) {
            uint32_t aofs = a_row * 128 + (((uint32_t)(kt * 32) + a_colH) ^ a_xor);
            uint32_t ah[4], al[4];
            ldsm4(ah, sb + AT_QH + aofs);
            ldsm4(al, sb + AT_QL + aofs);
#pragma unroll
            for (int np = 0; np < 4; ++np) {
                uint32_t brow = (uint32_t)(np * 16) + b_rowH;
                uint32_t bofs = brow * 128 +
                    (((uint32_t)(kt * 32) + b_colH) ^ ((brow & 7) << 4));
                uint32_t bh[4], bl[4];
                ldsm4(bh, kH + bofs);
                ldsm4(bl, kL + bofs);
                mma_f16(sacc[2 * np],     ah, bh[0], bh[1]);
                mma_f16(sacc[2 * np],     ah, bl[0], bl[1]);
                mma_f16(sacc[2 * np],     al, bh[0], bh[1]);
                mma_f16(sacc[2 * np + 1], ah, bh[2], bh[3]);
                mma_f16(sacc[2 * np + 1], ah, bl[2], bl[3]);
                mma_f16(sacc[2 * np + 1], al, bh[2], bh[3]);
            }
        }

        // ---- Mask (prefix + causal via kmax) + scale + online softmax ----
        float mx0 = -1e30f, mx1 = -1e30f;
#pragma unroll
        for (int j = 0; j < 8; ++j) {
            int k0 = kb * 64 + 8 * j + c0l, k1 = k0 + 1;
            float s0 = (k0 <= kmax0) ? sacc[j][0] * scale2 : -1e30f;
            float s1 = (k1 <= kmax0) ? sacc[j][1] * scale2 : -1e30f;
            float s2 = (k0 <= kmax1) ? sacc[j][2] * scale2 : -1e30f;
            float s3 = (k1 <= kmax1) ? sacc[j][3] * scale2 : -1e30f;
            sacc[j][0] = s0; sacc[j][1] = s1; sacc[j][2] = s2; sacc[j][3] = s3;
            mx0 = fmaxf(mx0, fmaxf(s0, s1));
            mx1 = fmaxf(mx1, fmaxf(s2, s3));
        }
        mx0 = fmaxf(mx0, __shfl_xor_sync(0xffffffffu, mx0, 1));
        mx0 = fmaxf(mx0, __shfl_xor_sync(0xffffffffu, mx0, 2));
        mx1 = fmaxf(mx1, __shfl_xor_sync(0xffffffffu, mx1, 1));
        mx1 = fmaxf(mx1, __shfl_xor_sync(0xffffffffu, mx1, 2));

        float mn0 = fmaxf(m0, mx0), mn1 = fmaxf(m1, mx1);
        float al0 = ex2(m0 - mn0), al1 = ex2(m1 - mn1);
        m0 = mn0; m1 = mn1;

        float rs0 = 0.f, rs1 = 0.f;
#pragma unroll
        for (int j = 0; j < 8; ++j) {
            sacc[j][0] = ex2(sacc[j][0] - mn0);
            sacc[j][1] = ex2(sacc[j][1] - mn0);
            sacc[j][2] = ex2(sacc[j][2] - mn1);
            sacc[j][3] = ex2(sacc[j][3] - mn1);
            rs0 += sacc[j][0] + sacc[j][1];
            rs1 += sacc[j][2] + sacc[j][3];
        }
        rs0 += __shfl_xor_sync(0xffffffffu, rs0, 1);
        rs0 += __shfl_xor_sync(0xffffffffu, rs0, 2);
        rs1 += __shfl_xor_sync(0xffffffffu, rs1, 1);
        rs1 += __shfl_xor_sync(0xffffffffu, rs1, 2);
        l0 = l0 * al0 + rs0;
        l1 = l1 * al1 + rs1;
#pragma unroll
        for (int j = 0; j < 8; ++j) {
            oacc[j][0] *= al0; oacc[j][1] *= al0;
            oacc[j][2] *= al1; oacc[j][3] *= al1;
        }

        // ---- O += P V (2-pass: (Ph+Pl) * Vh) ----
#pragma unroll
        for (int kt = 0; kt < 4; ++kt) {
            uint32_t ph[4], pl[4];
            cvt_hilo(sacc[2 * kt][0],     sacc[2 * kt][1],     ph[0], pl[0]);
            cvt_hilo(sacc[2 * kt][2],     sacc[2 * kt][3],     ph[1], pl[1]);
            cvt_hilo(sacc[2 * kt + 1][0], sacc[2 * kt + 1][1], ph[2], pl[2]);
            cvt_hilo(sacc[2 * kt + 1][2], sacc[2 * kt + 1][3], ph[3], pl[3]);
#pragma unroll
            for (int j2 = 0; j2 < 4; ++j2) {
                uint32_t vrow = (uint32_t)(kt * 16) + v_rowH;
                uint32_t vofs = vrow * 128 +
                    (((uint32_t)(j2 * 32) + v_colH) ^ v_xor);
                uint32_t vh[4];
                ldsm4t(vh, vH + vofs);
                mma_f16(oacc[2 * j2],     ph, vh[0], vh[1]);
                mma_f16(oacc[2 * j2],     pl, vh[0], vh[1]);
                mma_f16(oacc[2 * j2 + 1], ph, vh[2], vh[3]);
                mma_f16(oacc[2 * j2 + 1], pl, vh[2], vh[3]);
            }
        }
    }

    // ---- Epilogue: write hi/lo fp16 planes for GEMM2 ----
    float inv0 = 1.f / l0, inv1 = 1.f / l1;
    const size_t row0 = (size_t)b * TT + qb * 128 + wq + r;
#pragma unroll
    for (int j = 0; j < 8; ++j) {
        int col = h * DD + 8 * j + c0l;
        uint32_t hi0, lo0, hi1, lo1;
        cvt_hilo(oacc[j][0] * inv0, oacc[j][1] * inv0, hi0, lo0);
        cvt_hilo(oacc[j][2] * inv1, oacc[j][3] * inv1, hi1, lo1);
        *(uint32_t*)(g_ah + row0 * CC + col) = hi0;
        *(uint32_t*)(g_al + row0 * CC + col) = lo0;
        *(uint32_t*)(g_ah + (row0 + 8) * CC + col) = hi1;
        *(uint32_t*)(g_al + (row0 + 8) * CC + col) = lo1;
    }
}

// ---------------------------------------------------------------------------
// Launch
// ---------------------------------------------------------------------------
extern "C" void kernel_launch(void* const* d_in, const int* in_sizes, int n_in,
                              void* d_out, int out_size) {
    const float*         x     = (const float*)d_in[0];
    const unsigned char* mask  = (const unsigned char*)d_in[1];
    const float*         Wqkv  = (const float*)d_in[2];
    const float*         bqkv  = (const float*)d_in[3];
    const float*         Wproj = (const float*)d_in[4];
    const float*         bproj = (const float*)d_in[5];
    float*               out   = (float*)d_out;

    __half *xhi, *xlo, *wqh, *wql, *wph, *qkvh, *qkvl, *ahi, *alo;
    cudaGetSymbolAddress((void**)&xhi,  g_xhi);
    cudaGetSymbolAddress((void**)&xlo,  g_xlo);
    cudaGetSymbolAddress((void**)&wqh,  g_wqh);
    cudaGetSymbolAddress((void**)&wql,  g_wql);
    cudaGetSymbolAddress((void**)&wph,  g_wph);
    cudaGetSymbolAddress((void**)&qkvh, g_qkvh);
    cudaGetSymbolAddress((void**)&qkvl, g_qkvl);
    cudaGetSymbolAddress((void**)&ahi,  g_ah);
    cudaGetSymbolAddress((void**)&alo,  g_al);

    // 1. per-batch valid lengths
    len_kernel<<<BB, 256>>>(mask);

    // 2. merged splits
    {
        int total = NX_Q + NWQ_Q + NWP_Q;
        split_all_kernel<<<(total + 255) / 256, 256>>>(x, Wqkv, Wproj);
    }

    // 3. QKV projection: 3-pass (Q,K) / 2-pass (V), heavy-first 1D grid
    {
        const int dyn = 2 * 98304 + 1024;
        cudaFuncSetAttribute(gemm_mma_kernel<3, 1, 1>,
                             cudaFuncAttributeMaxDynamicSharedMemorySize, dyn);
        gemm_mma_kernel<3, 1, 1><<<384, 256, dyn>>>(
            xhi, xlo, wqh, wql, bqkv, nullptr, qkvh, qkvl, 3 * CC, 2 * CC);
    }

    // 4. Attention (sorted 1D grid, 2 CTAs/SM, triple-buffered)
    {
        cudaFuncSetAttribute(attn_mma_kernel,
                             cudaFuncAttributeMaxDynamicSharedMemorySize,
                             ATTN_DYN);
        attn_mma_kernel<<<512, 256, ATTN_DYN>>>();
    }

    // 5. Output projection: 2-pass, fp32 output (single wave: 128 CTAs)
    {
        const int dyn = 2 * 65536 + 1024;
        cudaFuncSetAttribute(gemm_mma_kernel<2, 0, 0>,
                             cudaFuncAttributeMaxDynamicSharedMemorySize, dyn);
        dim3 grid(CC / 256, MM / 128);
        gemm_mma_kernel<2, 0, 0><<<grid, 256, dyn>>>(
            ahi, alo, wph, wph, bproj, out, nullptr, nullptr, CC, 0);
    }
}